// round 7
// baseline (speedup 1.0000x reference)
#include <cuda_runtime.h>
#include <math.h>

// ---------------- problem constants ----------------
#define B_  2
#define S_  4096
#define D_  768
#define H_  12
#define DH_ 64
#define L_  2
#define F_  3072
#define C_  256
#define M_  (B_*S_)
#define NEGV (-1000000000.0f)

// ---------------- scratch ----------------
__device__ float g_h  [M_ * D_];
__device__ float g_q  [M_ * D_];
__device__ float g_k  [M_ * D_];
__device__ float g_v  [M_ * D_];
__device__ float g_ctx[M_ * D_];
__device__ float g_t  [M_ * D_];
__device__ float g_f  [M_ * F_];

// ---------------- helpers ----------------
__device__ __forceinline__ float warp_sum(float v) {
    #pragma unroll
    for (int o = 16; o; o >>= 1) v += __shfl_xor_sync(0xffffffffu, v, o);
    return v;
}
__device__ __forceinline__ float warp_max(float v) {
    #pragma unroll
    for (int o = 16; o; o >>= 1) v = fmaxf(v, __shfl_xor_sync(0xffffffffu, v, o));
    return v;
}
__device__ float block_sum(float v, float* red) {
    int lane = threadIdx.x & 31, w = threadIdx.x >> 5;
    v = warp_sum(v);
    __syncthreads();
    if (lane == 0) red[w] = v;
    __syncthreads();
    int nw = (blockDim.x + 31) >> 5;
    float r = (threadIdx.x < nw) ? red[threadIdx.x] : 0.0f;
    if (w == 0) { r = warp_sum(r); if (lane == 0) red[0] = r; }
    __syncthreads();
    return red[0];
}
__device__ float block_max(float v, float* red) {
    int lane = threadIdx.x & 31, w = threadIdx.x >> 5;
    v = warp_max(v);
    __syncthreads();
    if (lane == 0) red[w] = v;
    __syncthreads();
    int nw = (blockDim.x + 31) >> 5;
    float r = (threadIdx.x < nw) ? red[threadIdx.x] : -INFINITY;
    if (w == 0) { r = warp_max(r); if (lane == 0) red[0] = r; }
    __syncthreads();
    return red[0];
}

__device__ __forceinline__ float f2tff(float v) {
    unsigned r; asm("cvt.rna.tf32.f32 %0, %1;" : "=r"(r) : "f"(v));
    return __uint_as_float(r);
}
__device__ __forceinline__ unsigned f2tf(float v) {
    unsigned r; asm("cvt.rna.tf32.f32 %0, %1;" : "=r"(r) : "f"(v)); return r;
}
__device__ __forceinline__ void mma_tf32(float* c, const unsigned* a, const unsigned* b) {
    asm volatile(
        "mma.sync.aligned.m16n8k8.row.col.f32.tf32.tf32.f32 "
        "{%0,%1,%2,%3},{%4,%5,%6,%7},{%8,%9},{%0,%1,%2,%3};\n"
        : "+f"(c[0]), "+f"(c[1]), "+f"(c[2]), "+f"(c[3])
        : "r"(a[0]), "r"(a[1]), "r"(a[2]), "r"(a[3]), "r"(b[0]), "r"(b[1]));
}
__device__ __forceinline__ void cp_async16(unsigned smem, const void* g) {
    asm volatile("cp.async.ca.shared.global [%0], [%1], 16;\n" :: "r"(smem), "l"(g));
}

// ---------------- embedding + layernorm (tf32-rounded output) ----------------
__global__ void embed_ln_kernel(const int* __restrict__ ids,
                                const float* __restrict__ tok,
                                const float* __restrict__ pos,
                                const float* __restrict__ g,
                                const float* __restrict__ be,
                                float* __restrict__ out) {
    __shared__ float red[32];
    int row = blockIdx.x;
    int s = row % S_;
    int id = ids[row];
    const float* tp = tok + (size_t)id * D_;
    const float* pp = pos + (size_t)s  * D_;
    float vals[3]; float lsum = 0.0f;
    #pragma unroll
    for (int i = 0; i < 3; i++) {
        int c = threadIdx.x + i * 256;
        vals[i] = tp[c] + pp[c];
        lsum += vals[i];
    }
    float mean = block_sum(lsum, red) * (1.0f / D_);
    float lv = 0.0f;
    #pragma unroll
    for (int i = 0; i < 3; i++) { float d = vals[i] - mean; lv += d * d; }
    float var = block_sum(lv, red) * (1.0f / D_);
    float inv = rsqrtf(var + 1e-5f);
    float* op = out + (size_t)row * D_;
    #pragma unroll
    for (int i = 0; i < 3; i++) {
        int c = threadIdx.x + i * 256;
        op[c] = f2tff((vals[i] - mean) * inv * g[c] + be[c]);
    }
}

// ---------------- residual add + layernorm (tf32-rounded output) ----------------
__global__ void add_ln_kernel(const float* __restrict__ x,
                              const float* __restrict__ r,
                              const float* __restrict__ g,
                              const float* __restrict__ be,
                              float* __restrict__ out) {
    __shared__ float red[32];
    int row = blockIdx.x;
    const float* xp = x + (size_t)row * D_;
    const float* rp = r + (size_t)row * D_;
    float vals[3]; float lsum = 0.0f;
    #pragma unroll
    for (int i = 0; i < 3; i++) {
        int c = threadIdx.x + i * 256;
        vals[i] = xp[c] + rp[c];
        lsum += vals[i];
    }
    float mean = block_sum(lsum, red) * (1.0f / D_);
    float lv = 0.0f;
    #pragma unroll
    for (int i = 0; i < 3; i++) { float d = vals[i] - mean; lv += d * d; }
    float var = block_sum(lv, red) * (1.0f / D_);
    float inv = rsqrtf(var + 1e-5f);
    float* op = out + (size_t)row * D_;
    #pragma unroll
    for (int i = 0; i < 3; i++) {
        int c = threadIdx.x + i * 256;
        op[c] = f2tff((vals[i] - mean) * inv * g[c] + be[c]);
    }
}

// ---------------- tf32 mma GEMM, 128x128 tile, 256 threads, vectorized frags ----------------
// A (activations) already tf32-rounded by producers -> staged raw via cp.async, [m][k] stride 20.
// B (weights) cvt'd during reg-prefetch staging -> [n][k] transposed, chunk-XOR swizzled.
// k-slot remap: mma slot ti covers phys k {4ti, 4ti+1} (mma0) / {4ti+2, 4ti+3} (mma1),
// so every fragment is a single LDS.128.
#define GSTR 20

__global__ __launch_bounds__(256, 2) void gemm_tf32_kernel(
        const float* __restrict__ A, const float* __restrict__ W,
        const float* __restrict__ bias, float* __restrict__ Co,
        int M, int N, int K, int act, float scale) {
    __shared__ unsigned As[2][128 * GSTR];
    __shared__ unsigned Bs[2][128 * GSTR];

    int tid = threadIdx.x;
    int lane = tid & 31, wid = tid >> 5;
    int gid = lane >> 2, ti = lane & 3;
    int wm = (wid & 3) * 32;
    int wn = (wid >> 2) * 64;
    size_t rowBase = (size_t)blockIdx.y * 128;
    size_t colBase = (size_t)blockIdx.x * 128;

    // A staging slots (512 16B-chunks, 2 per thread)
    int ar = tid >> 2, ach = (tid & 3) * 4;

    // B staging slots
    int bn = tid & 127;
    int bkh = (tid >> 7) * 8;            // k half: 0 or 8
    int bsw = (bn >> 3) & 3;
    int bc0 = ((bkh >> 2) + 0) ^ bsw;
    int bc1 = ((bkh >> 2) + 1) ^ bsw;

    float c[2][8][4];
    #pragma unroll
    for (int mi = 0; mi < 2; mi++)
        #pragma unroll
        for (int ni = 0; ni < 8; ni++)
            #pragma unroll
            for (int q = 0; q < 4; q++) c[mi][ni][q] = 0.0f;

    int nt = K / 16;
    unsigned breg[8];

    // ---- prologue: tile 0 ----
    #pragma unroll
    for (int p = 0; p < 2; p++) {
        int row = ar + p * 64;
        unsigned sa = (unsigned)__cvta_generic_to_shared(&As[0][row * GSTR + ach]);
        cp_async16(sa, &A[(rowBase + row) * K + ach]);
    }
    asm volatile("cp.async.commit_group;\n");
    #pragma unroll
    for (int kk = 0; kk < 8; kk++)
        breg[kk] = f2tf(W[(size_t)(bkh + kk) * N + colBase + bn]);
    *(uint4*)&Bs[0][bn * GSTR + bc0 * 4] = make_uint4(breg[0], breg[1], breg[2], breg[3]);
    *(uint4*)&Bs[0][bn * GSTR + bc1 * 4] = make_uint4(breg[4], breg[5], breg[6], breg[7]);
    asm volatile("cp.async.wait_group 0;\n");
    __syncthreads();

    for (int kt = 0; kt < nt; kt++) {
        int cur = kt & 1, nxt = cur ^ 1;
        bool hasNext = (kt + 1) < nt;
        if (hasNext) {
            int k0n = (kt + 1) * 16;
            #pragma unroll
            for (int p = 0; p < 2; p++) {
                int row = ar + p * 64;
                unsigned sa = (unsigned)__cvta_generic_to_shared(&As[nxt][row * GSTR + ach]);
                cp_async16(sa, &A[(rowBase + row) * K + k0n + ach]);
            }
            asm volatile("cp.async.commit_group;\n");
            #pragma unroll
            for (int kk = 0; kk < 8; kk++)
                breg[kk] = f2tf(W[(size_t)(k0n + bkh + kk) * N + colBase + bn]);
        }

        // fragments (all LDS.128) + mma
        uint4 a4[2][2];
        #pragma unroll
        for (int mi = 0; mi < 2; mi++)
            #pragma unroll
            for (int rh = 0; rh < 2; rh++)
                a4[mi][rh] = *(uint4*)&As[cur][(wm + mi * 16 + rh * 8 + gid) * GSTR + ti * 4];

        #pragma unroll
        for (int ni = 0; ni < 8; ni++) {
            uint4 b4 = *(uint4*)&Bs[cur][(wn + ni * 8 + gid) * GSTR + ((ti ^ (ni & 3)) * 4)];
            unsigned bb0[2] = {b4.x, b4.y};
            unsigned bb1[2] = {b4.z, b4.w};
            #pragma unroll
            for (int mi = 0; mi < 2; mi++) {
                unsigned aa0[4] = {a4[mi][0].x, a4[mi][1].x, a4[mi][0].y, a4[mi][1].y};
                mma_tf32(c[mi][ni], aa0, bb0);
                unsigned aa1[4] = {a4[mi][0].z, a4[mi][1].z, a4[mi][0].w, a4[mi][1].w};
                mma_tf32(c[mi][ni], aa1, bb1);
            }
        }

        if (hasNext) {
            *(uint4*)&Bs[nxt][bn * GSTR + bc0 * 4] = make_uint4(breg[0], breg[1], breg[2], breg[3]);
            *(uint4*)&Bs[nxt][bn * GSTR + bc1 * 4] = make_uint4(breg[4], breg[5], breg[6], breg[7]);
            asm volatile("cp.async.wait_group 0;\n");
        }
        __syncthreads();
    }

    // epilogue (tf32-rounded output)
    #pragma unroll
    for (int mi = 0; mi < 2; mi++) {
        size_t r0 = rowBase + wm + mi * 16 + gid;
        size_t r1 = r0 + 8;
        #pragma unroll
        for (int ni = 0; ni < 8; ni++) {
            size_t col = colBase + wn + ni * 8 + ti * 2;
            float b0 = bias[col], b1 = bias[col + 1];
            float v0 = (c[mi][ni][0] + b0) * scale;
            float v1 = (c[mi][ni][1] + b1) * scale;
            float v2 = (c[mi][ni][2] + b0) * scale;
            float v3 = (c[mi][ni][3] + b1) * scale;
            if (act == 1) {
                v0 = 0.5f * v0 * (1.0f + erff(v0 * 0.70710678f));
                v1 = 0.5f * v1 * (1.0f + erff(v1 * 0.70710678f));
                v2 = 0.5f * v2 * (1.0f + erff(v2 * 0.70710678f));
                v3 = 0.5f * v3 * (1.0f + erff(v3 * 0.70710678f));
            }
            *(float2*)&Co[r0 * N + col] = make_float2(f2tff(v0), f2tff(v1));
            *(float2*)&Co[r1 * N + col] = make_float2(f2tff(v2), f2tff(v3));
        }
    }
}

// ---------------- sliding-window attention (tensor-core) ----------------
#define SCW2 772
#define AT_Q   0
#define AT_KV  2176
#define AT_SC  6528
#define AT_INV 31232
#define AT_MV  31264
#define AT_SMEM ((31328) * 4)

__global__ __launch_bounds__(256) void sw_attn_kernel(
        const float* __restrict__ q,
        const float* __restrict__ k,
        const float* __restrict__ v,
        const int* __restrict__ mask,
        float* __restrict__ ctx) {
    extern __shared__ float sm[];
    unsigned* qU  = (unsigned*)(sm + AT_Q);
    unsigned* kvU = (unsigned*)(sm + AT_KV);
    float* sc  = sm + AT_SC;
    float* inv = sm + AT_INV;
    float* mv  = sm + AT_MV;
    unsigned* scU = (unsigned*)sc;

    int tid = threadIdx.x;
    int lane = tid & 31, w = tid >> 5;
    int gid = lane >> 2, ti = lane & 3;
    int h = blockIdx.y, b = blockIdx.z;
    int qbase = blockIdx.x * 32;
    int n = qbase / C_;
    int cbase = qbase % C_;
    int j0 = (n - 1) * C_;
    int n0 = w * 8;

    #pragma unroll
    for (int p = 0; p < 2; p++) {
        int s = tid + p * 256;
        int r = s >> 4, c4 = (s & 15) * 4;
        float4 qv = *(const float4*)&q[((size_t)(b * S_ + qbase + r)) * D_ + h * DH_ + c4];
        qU[r * 68 + c4 + 0] = f2tf(qv.x);
        qU[r * 68 + c4 + 1] = f2tf(qv.y);
        qU[r * 68 + c4 + 2] = f2tf(qv.z);
        qU[r * 68 + c4 + 3] = f2tf(qv.w);
    }
    __syncthreads();

    unsigned aF[2][8][4];
    #pragma unroll
    for (int mi = 0; mi < 2; mi++)
        #pragma unroll
        for (int ks = 0; ks < 8; ks++) {
            const unsigned* ap = &qU[(mi * 16 + gid) * 68 + ks * 8 + ti];
            aF[mi][ks][0] = ap[0];
            aF[mi][ks][1] = ap[8 * 68];
            aF[mi][ks][2] = ap[4];
            aF[mi][ks][3] = ap[8 * 68 + 4];
        }

    for (int kt = 0; kt < 12; kt++) {
        __syncthreads();
        #pragma unroll
        for (int p = 0; p < 4; p++) {
            int s = tid + p * 256;
            int r = s >> 4, c4 = (s & 15) * 4;
            int j = j0 + kt * 64 + r;
            float4 kvv = make_float4(0.f, 0.f, 0.f, 0.f);
            if (j >= 0 && j < S_)
                kvv = *(const float4*)&k[((size_t)(b * S_ + j)) * D_ + h * DH_ + c4];
            unsigned* kp = &kvU[r * 68 + c4];
            kp[0] = f2tf(kvv.x); kp[1] = f2tf(kvv.y);
            kp[2] = f2tf(kvv.z); kp[3] = f2tf(kvv.w);
            if (c4 == 0)
                mv[r] = (j > 0 && j < S_ && mask[b * S_ + j] > 0) ? 1.0f : 0.0f;
        }
        __syncthreads();

        float cS[2][4];
        #pragma unroll
        for (int mi = 0; mi < 2; mi++)
            #pragma unroll
            for (int qq = 0; qq < 4; qq++) cS[mi][qq] = 0.0f;

        #pragma unroll
        for (int ks = 0; ks < 8; ks++) {
            unsigned bb[2];
            bb[0] = kvU[(n0 + gid) * 68 + ks * 8 + ti];
            bb[1] = kvU[(n0 + gid) * 68 + ks * 8 + ti + 4];
            mma_tf32(cS[0], aF[0][ks], bb);
            mma_tf32(cS[1], aF[1][ks], bb);
        }

        int kk0 = kt * 64 + n0 + 2 * ti;
        float valid0 = mv[n0 + 2 * ti], valid1 = mv[n0 + 2 * ti + 1];
        #pragma unroll
        for (int mi = 0; mi < 2; mi++) {
            int r0 = mi * 16 + gid, r1 = r0 + 8;
            int cq0 = cbase + r0, cq1 = cbase + r1;
            bool ok00 = (valid0 > 0.5f) && (kk0 >= cq0) && (kk0 <= cq0 + 2 * C_);
            bool ok01 = (valid1 > 0.5f) && (kk0 + 1 >= cq0) && (kk0 + 1 <= cq0 + 2 * C_);
            bool ok10 = (valid0 > 0.5f) && (kk0 >= cq1) && (kk0 <= cq1 + 2 * C_);
            bool ok11 = (valid1 > 0.5f) && (kk0 + 1 >= cq1) && (kk0 + 1 <= cq1 + 2 * C_);
            sc[r0 * SCW2 + kk0]     = ok00 ? cS[mi][0] : NEGV;
            sc[r0 * SCW2 + kk0 + 1] = ok01 ? cS[mi][1] : NEGV;
            sc[r1 * SCW2 + kk0]     = ok10 ? cS[mi][2] : NEGV;
            sc[r1 * SCW2 + kk0 + 1] = ok11 ? cS[mi][3] : NEGV;
        }
    }

    if (tid < 32) {
        float acc = 0.0f;
        const float* k0p = k + ((size_t)(b * S_)) * D_ + h * DH_;
        #pragma unroll 8
        for (int d = 0; d < 64; d++)
            acc = fmaf(__uint_as_float(qU[tid * 68 + d]), k0p[d], acc);
        sc[tid * SCW2 + 3 * C_] = (mask[b * S_] > 0) ? acc : NEGV;
    }
    __syncthreads();

    for (int rr = 0; rr < 4; rr++) {
        int qi = w + rr * 8;
        float* row = sc + qi * SCW2;
        float m = -INFINITY;
        for (int j = lane; j < 3 * C_ + 1; j += 32) m = fmaxf(m, row[j]);
        m = warp_max(m);
        float ssum = 0.0f;
        for (int j = lane; j < 3 * C_ + 1; j += 32) {
            float e = __expf(row[j] - m);
            ssum += e;
            row[j] = __uint_as_float(f2tf(e));
        }
        ssum = warp_sum(ssum);
        if (lane == 0) inv[qi] = 1.0f / ssum;
    }

    float cO[2][4];
    #pragma unroll
    for (int mi = 0; mi < 2; mi++)
        #pragma unroll
        for (int qq = 0; qq < 4; qq++) cO[mi][qq] = 0.0f;

    for (int kt = 0; kt < 12; kt++) {
        __syncthreads();
        #pragma unroll
        for (int p = 0; p < 4; p++) {
            int s = tid + p * 256;
            int r = s >> 4, c4 = (s & 15) * 4;
            int j = j0 + kt * 64 + r;
            float4 vv = make_float4(0.f, 0.f, 0.f, 0.f);
            if (j >= 0 && j < S_)
                vv = *(const float4*)&v[((size_t)(b * S_ + j)) * D_ + h * DH_ + c4];
            kvU[(c4 + 0) * 68 + (r ^ ((c4 + 0) >> 3))] = f2tf(vv.x);
            kvU[(c4 + 1) * 68 + (r ^ ((c4 + 1) >> 3))] = f2tf(vv.y);
            kvU[(c4 + 2) * 68 + (r ^ ((c4 + 2) >> 3))] = f2tf(vv.z);
            kvU[(c4 + 3) * 68 + (r ^ ((c4 + 3) >> 3))] = f2tf(vv.w);
        }
        __syncthreads();

        #pragma unroll
        for (int ks = 0; ks < 8; ks++) {
            unsigned bb[2];
            int drow = n0 + gid;
            bb[0] = kvU[drow * 68 + ((ks * 8 + ti) ^ w)];
            bb[1] = kvU[drow * 68 + ((ks * 8 + ti + 4) ^ w)];
            #pragma unroll
            for (int mi = 0; mi < 2; mi++) {
                unsigned aa[4];
                const unsigned* pp = &scU[(mi * 16 + gid) * SCW2 + kt * 64 + ks * 8 + ti];
                aa[0] = pp[0];
                aa[1] = pp[8 * SCW2];
                aa[2] = pp[4];
                aa[3] = pp[8 * SCW2 + 4];
                mma_tf32(cO[mi], aa, bb);
            }
        }
    }

    {
        const float* v0p = v + ((size_t)(b * S_)) * D_ + h * DH_;
        int d0 = n0 + 2 * ti;
        float gv0 = v0p[d0], gv1 = v0p[d0 + 1];
        #pragma unroll
        for (int mi = 0; mi < 2; mi++) {
            int r0 = mi * 16 + gid, r1 = r0 + 8;
            float g0 = sc[r0 * SCW2 + 3 * C_], g1 = sc[r1 * SCW2 + 3 * C_];
            float i0 = inv[r0], i1 = inv[r1];
            float2 o0 = make_float2(f2tff((cO[mi][0] + g0 * gv0) * i0),
                                    f2tff((cO[mi][1] + g0 * gv1) * i0));
            float2 o1 = make_float2(f2tff((cO[mi][2] + g1 * gv0) * i1),
                                    f2tff((cO[mi][3] + g1 * gv1) * i1));
            *(float2*)&ctx[((size_t)(b * S_ + qbase + r0)) * D_ + h * DH_ + d0] = o0;
            *(float2*)&ctx[((size_t)(b * S_ + qbase + r1)) * D_ + h * DH_ + d0] = o1;
        }
    }
}

// ---------------- full attention for query row 0 ----------------
__global__ void global_attn_kernel(const float* __restrict__ q,
                                   const float* __restrict__ k,
                                   const float* __restrict__ v,
                                   const int* __restrict__ mask,
                                   float* __restrict__ ctx) {
    __shared__ float qs[64];
    __shared__ float sc[S_];
    __shared__ float red[32];
    __shared__ float cpart[256];
    int h = blockIdx.x, b = blockIdx.y;
    int tid = threadIdx.x;
    const float* qp = q + ((size_t)(b * S_)) * D_ + h * DH_;
    if (tid < 16) ((float4*)qs)[tid] = ((const float4*)qp)[tid];
    __syncthreads();

    for (int j = tid; j < S_; j += 256) {
        float s = NEGV;
        if (mask[b * S_ + j] > 0) {
            const float4* kp = (const float4*)(k + ((size_t)(b * S_ + j)) * D_ + h * DH_);
            float acc = 0.0f;
            #pragma unroll
            for (int d4 = 0; d4 < 16; d4++) {
                float4 kvv = kp[d4];
                float4 qv = ((const float4*)qs)[d4];
                acc += kvv.x * qv.x + kvv.y * qv.y + kvv.z * qv.z + kvv.w * qv.w;
            }
            s = acc;
        }
        sc[j] = s;
    }
    __syncthreads();

    float m = -INFINITY;
    for (int j = tid; j < S_; j += 256) m = fmaxf(m, sc[j]);
    m = block_max(m, red);
    float lsum = 0.0f;
    for (int j = tid; j < S_; j += 256) {
        float e = __expf(sc[j] - m);
        sc[j] = e;
        lsum += e;
    }
    float sum = block_sum(lsum, red);
    float inv = 1.0f / sum;

    int d = tid & 63, part = tid >> 6;
    float accum = 0.0f;
    for (int j = part; j < S_; j += 4)
        accum += sc[j] * v[((size_t)(b * S_ + j)) * D_ + h * DH_ + d];
    cpart[tid] = accum;
    __syncthreads();
    if (part == 0)
        ctx[((size_t)(b * S_)) * D_ + h * DH_ + d] =
            f2tff((cpart[d] + cpart[64 + d] + cpart[128 + d] + cpart[192 + d]) * inv);
}

// ---------------- classifier head ----------------
__global__ void cls_kernel(const float* __restrict__ h,
                           const float* __restrict__ W,
                           const float* __restrict__ bias,
                           float* __restrict__ out) {
    int w = threadIdx.x >> 5, lane = threadIdx.x & 31;
    if (w < B_ * 3) {
        int b = w / 3, c = w % 3;
        float acc = 0.0f;
        for (int kx = lane; kx < D_; kx += 32)
            acc += h[((size_t)(b * S_)) * D_ + kx] * W[kx * 3 + c];
        acc = warp_sum(acc);
        if (lane == 0) out[b * 3 + c] = acc + bias[c];
    }
}

// ---------------- launch ----------------
extern "C" void kernel_launch(void* const* d_in, const int* in_sizes, int n_in,
                              void* d_out, int out_size) {
    const int*   ids      = (const int*)d_in[0];
    const int*   mask     = (const int*)d_in[1];
    const float* emb_tok  = (const float*)d_in[2];
    const float* emb_pos  = (const float*)d_in[3];
    const float* emb_ln_g = (const float*)d_in[4];
    const float* emb_ln_b = (const float*)d_in[5];
    const float* Wq = (const float*)d_in[6];
    const float* bq = (const float*)d_in[7];
    const float* Wk = (const float*)d_in[8];
    const float* bk = (const float*)d_in[9];
    const float* Wv = (const float*)d_in[10];
    const float* bv = (const float*)d_in[11];
    const float* Wo = (const float*)d_in[12];
    const float* bo = (const float*)d_in[13];
    const float* ln1_g = (const float*)d_in[14];
    const float* ln1_b = (const float*)d_in[15];
    const float* W1 = (const float*)d_in[16];
    const float* b1 = (const float*)d_in[17];
    const float* W2 = (const float*)d_in[18];
    const float* b2 = (const float*)d_in[19];
    const float* ln2_g = (const float*)d_in[20];
    const float* ln2_b = (const float*)d_in[21];
    const float* clsW = (const float*)d_in[22];
    const float* clsb = (const float*)d_in[23];

    float *h, *q, *k, *v, *ctx, *t, *f;
    cudaGetSymbolAddress((void**)&h,   g_h);
    cudaGetSymbolAddress((void**)&q,   g_q);
    cudaGetSymbolAddress((void**)&k,   g_k);
    cudaGetSymbolAddress((void**)&v,   g_v);
    cudaGetSymbolAddress((void**)&ctx, g_ctx);
    cudaGetSymbolAddress((void**)&t,   g_t);
    cudaGetSymbolAddress((void**)&f,   g_f);

    static int attr_done = 0;
    if (!attr_done) {
        cudaFuncSetAttribute(sw_attn_kernel,
                             cudaFuncAttributeMaxDynamicSharedMemorySize, AT_SMEM);
        attr_done = 1;
    }

    embed_ln_kernel<<<M_, 256>>>(ids, emb_tok, emb_pos, emb_ln_g, emb_ln_b, h);

    for (int l = 0; l < L_; l++) {
        const float* Wql = Wq + (size_t)l * D_ * D_;
        const float* Wkl = Wk + (size_t)l * D_ * D_;
        const float* Wvl = Wv + (size_t)l * D_ * D_;
        const float* Wol = Wo + (size_t)l * D_ * D_;
        const float* W1l = W1 + (size_t)l * D_ * F_;
        const float* W2l = W2 + (size_t)l * F_ * D_;

        dim3 gD(D_ / 128, M_ / 128);
        dim3 gF(F_ / 128, M_ / 128);

        gemm_tf32_kernel<<<gD, 256>>>(h, Wql, bq + l * D_, q, M_, D_, D_, 0, 0.125f);
        gemm_tf32_kernel<<<gD, 256>>>(h, Wkl, bk + l * D_, k, M_, D_, D_, 0, 1.0f);
        gemm_tf32_kernel<<<gD, 256>>>(h, Wvl, bv + l * D_, v, M_, D_, D_, 0, 1.0f);

        sw_attn_kernel<<<dim3(S_ / 32, H_, B_), 256, AT_SMEM>>>(q, k, v, mask, ctx);
        global_attn_kernel<<<dim3(H_, B_), 256>>>(q, k, v, mask, ctx);

        gemm_tf32_kernel<<<gD, 256>>>(ctx, Wol, bo + l * D_, t, M_, D_, D_, 0, 1.0f);
        add_ln_kernel<<<M_, 256>>>(h, t, ln1_g + l * D_, ln1_b + l * D_, h);

        gemm_tf32_kernel<<<gF, 256>>>(h, W1l, b1 + l * F_, f, M_, F_, D_, 1, 1.0f);
        gemm_tf32_kernel<<<gD, 256>>>(f, W2l, b2 + l * D_, t, M_, D_, F_, 0, 1.0f);
        add_ln_kernel<<<M_, 256>>>(h, t, ln2_g + l * D_, ln2_b + l * D_, h);
    }

    cls_kernel<<<1, 256>>>(h, clsW, clsb, (float*)d_out);
}

// round 12
// speedup vs baseline: 1.5951x; 1.5951x over previous
#include <cuda_runtime.h>
#include <math.h>

// ---------------- problem constants ----------------
#define B_  2
#define S_  4096
#define D_  768
#define H_  12
#define DH_ 64
#define L_  2
#define F_  3072
#define C_  256
#define M_  (B_*S_)
#define NEGV (-1000000000.0f)

// ---------------- scratch ----------------
__device__ float g_h  [M_ * D_];
__device__ float g_q  [M_ * D_];
__device__ float g_k  [M_ * D_];
__device__ float g_v  [M_ * D_];
__device__ float g_ctx[M_ * D_];
__device__ float g_t  [M_ * D_];
__device__ float g_f  [M_ * F_];

// ---------------- helpers ----------------
__device__ __forceinline__ float warp_sum(float v) {
    #pragma unroll
    for (int o = 16; o; o >>= 1) v += __shfl_xor_sync(0xffffffffu, v, o);
    return v;
}
__device__ __forceinline__ float warp_max(float v) {
    #pragma unroll
    for (int o = 16; o; o >>= 1) v = fmaxf(v, __shfl_xor_sync(0xffffffffu, v, o));
    return v;
}
__device__ float block_sum(float v, float* red) {
    int lane = threadIdx.x & 31, w = threadIdx.x >> 5;
    v = warp_sum(v);
    __syncthreads();
    if (lane == 0) red[w] = v;
    __syncthreads();
    int nw = (blockDim.x + 31) >> 5;
    float r = (threadIdx.x < nw) ? red[threadIdx.x] : 0.0f;
    if (w == 0) { r = warp_sum(r); if (lane == 0) red[0] = r; }
    __syncthreads();
    return red[0];
}
__device__ float block_max(float v, float* red) {
    int lane = threadIdx.x & 31, w = threadIdx.x >> 5;
    v = warp_max(v);
    __syncthreads();
    if (lane == 0) red[w] = v;
    __syncthreads();
    int nw = (blockDim.x + 31) >> 5;
    float r = (threadIdx.x < nw) ? red[threadIdx.x] : -INFINITY;
    if (w == 0) { r = warp_max(r); if (lane == 0) red[0] = r; }
    __syncthreads();
    return red[0];
}

__device__ __forceinline__ unsigned f2tf(float v) {
    unsigned r; asm("cvt.rna.tf32.f32 %0, %1;" : "=r"(r) : "f"(v)); return r;
}
__device__ __forceinline__ void mma_tf32(float* c, const unsigned* a, const unsigned* b) {
    asm volatile(
        "mma.sync.aligned.m16n8k8.row.col.f32.tf32.tf32.f32 "
        "{%0,%1,%2,%3},{%4,%5,%6,%7},{%8,%9},{%0,%1,%2,%3};\n"
        : "+f"(c[0]), "+f"(c[1]), "+f"(c[2]), "+f"(c[3])
        : "r"(a[0]), "r"(a[1]), "r"(a[2]), "r"(a[3]), "r"(b[0]), "r"(b[1]));
}

// ---------------- embedding + layernorm ----------------
__global__ void embed_ln_kernel(const int* __restrict__ ids,
                                const float* __restrict__ tok,
                                const float* __restrict__ pos,
                                const float* __restrict__ g,
                                const float* __restrict__ be,
                                float* __restrict__ out) {
    __shared__ float red[32];
    int row = blockIdx.x;
    int s = row % S_;
    int id = ids[row];
    const float* tp = tok + (size_t)id * D_;
    const float* pp = pos + (size_t)s  * D_;
    float vals[3]; float lsum = 0.0f;
    #pragma unroll
    for (int i = 0; i < 3; i++) {
        int c = threadIdx.x + i * 256;
        vals[i] = tp[c] + pp[c];
        lsum += vals[i];
    }
    float mean = block_sum(lsum, red) * (1.0f / D_);
    float lv = 0.0f;
    #pragma unroll
    for (int i = 0; i < 3; i++) { float d = vals[i] - mean; lv += d * d; }
    float var = block_sum(lv, red) * (1.0f / D_);
    float inv = rsqrtf(var + 1e-5f);
    float* op = out + (size_t)row * D_;
    #pragma unroll
    for (int i = 0; i < 3; i++) {
        int c = threadIdx.x + i * 256;
        op[c] = (vals[i] - mean) * inv * g[c] + be[c];
    }
}

// ---------------- residual add + layernorm ----------------
__global__ void add_ln_kernel(const float* __restrict__ x,
                              const float* __restrict__ r,
                              const float* __restrict__ g,
                              const float* __restrict__ be,
                              float* __restrict__ out) {
    __shared__ float red[32];
    int row = blockIdx.x;
    const float* xp = x + (size_t)row * D_;
    const float* rp = r + (size_t)row * D_;
    float vals[3]; float lsum = 0.0f;
    #pragma unroll
    for (int i = 0; i < 3; i++) {
        int c = threadIdx.x + i * 256;
        vals[i] = xp[c] + rp[c];
        lsum += vals[i];
    }
    float mean = block_sum(lsum, red) * (1.0f / D_);
    float lv = 0.0f;
    #pragma unroll
    for (int i = 0; i < 3; i++) { float d = vals[i] - mean; lv += d * d; }
    float var = block_sum(lv, red) * (1.0f / D_);
    float inv = rsqrtf(var + 1e-5f);
    float* op = out + (size_t)row * D_;
    #pragma unroll
    for (int i = 0; i < 3; i++) {
        int c = threadIdx.x + i * 256;
        op[c] = (vals[i] - mean) * inv * g[c] + be[c];
    }
}

// ---------------- tf32 mma GEMM (R3 layout; cvt at smem store) ----------------
// blockIdx.z selects among up to 3 (W, bias, out, scale) sets (fused QKV).
#define TBM 128
#define TBN 128
#define TBK 16
#define ASTR 20
#define BSTR 132

__global__ __launch_bounds__(256) void gemm_tf32_kernel(
        const float* __restrict__ A,
        const float* __restrict__ W0, const float* __restrict__ W1p,
        const float* __restrict__ W2p,
        const float* __restrict__ bi0, const float* __restrict__ bi1,
        const float* __restrict__ bi2,
        float* __restrict__ C0, float* __restrict__ C1, float* __restrict__ C2,
        int M, int N, int K, int act, float s0, float s1, float s2) {
    __shared__ unsigned As[2][TBM * ASTR];
    __shared__ unsigned Bs[2][TBK * BSTR];

    int z = blockIdx.z;
    const float* W    = (z == 0) ? W0  : (z == 1) ? W1p : W2p;
    const float* bias = (z == 0) ? bi0 : (z == 1) ? bi1 : bi2;
    float*       Co   = (z == 0) ? C0  : (z == 1) ? C1  : C2;
    float scale       = (z == 0) ? s0  : (z == 1) ? s1  : s2;

    int tid = threadIdx.x;
    int lane = tid & 31, wid = tid >> 5;
    int wm = (wid & 3) * 32;
    int wn = (wid >> 2) * 64;
    int gid = lane >> 2, tig = lane & 3;
    size_t rowBase = (size_t)blockIdx.y * TBM;
    size_t colBase = (size_t)blockIdx.x * TBN;

    int s0i = tid, s1i = tid + 256;
    int ar0 = s0i >> 2, ac0 = (s0i & 3) * 4;
    int ar1 = s1i >> 2, ac1 = (s1i & 3) * 4;
    int br0 = s0i >> 5, bc0 = (s0i & 31) * 4;
    int br1 = s1i >> 5, bc1 = (s1i & 31) * 4;

    float c[2][8][4];
    #pragma unroll
    for (int mi = 0; mi < 2; mi++)
        #pragma unroll
        for (int ni = 0; ni < 8; ni++)
            #pragma unroll
            for (int q = 0; q < 4; q++) c[mi][ni][q] = 0.0f;

    int ntiles = K / TBK;

    float4 aPre0, aPre1, bPre0, bPre1;
    aPre0 = *(const float4*)&A[(rowBase + ar0) * K + ac0];
    aPre1 = *(const float4*)&A[(rowBase + ar1) * K + ac1];
    bPre0 = *(const float4*)&W[(size_t)br0 * N + colBase + bc0];
    bPre1 = *(const float4*)&W[(size_t)br1 * N + colBase + bc1];
    {
        unsigned* p;
        p = &As[0][ar0 * ASTR + ac0];
        p[0]=f2tf(aPre0.x); p[1]=f2tf(aPre0.y); p[2]=f2tf(aPre0.z); p[3]=f2tf(aPre0.w);
        p = &As[0][ar1 * ASTR + ac1];
        p[0]=f2tf(aPre1.x); p[1]=f2tf(aPre1.y); p[2]=f2tf(aPre1.z); p[3]=f2tf(aPre1.w);
        p = &Bs[0][br0 * BSTR + bc0];
        p[0]=f2tf(bPre0.x); p[1]=f2tf(bPre0.y); p[2]=f2tf(bPre0.z); p[3]=f2tf(bPre0.w);
        p = &Bs[0][br1 * BSTR + bc1];
        p[0]=f2tf(bPre1.x); p[1]=f2tf(bPre1.y); p[2]=f2tf(bPre1.z); p[3]=f2tf(bPre1.w);
    }
    __syncthreads();

    for (int kt = 0; kt < ntiles; kt++) {
        int cur = kt & 1;
        bool hasNext = (kt + 1) < ntiles;
        if (hasNext) {
            int k0 = (kt + 1) * TBK;
            aPre0 = *(const float4*)&A[(rowBase + ar0) * K + k0 + ac0];
            aPre1 = *(const float4*)&A[(rowBase + ar1) * K + k0 + ac1];
            bPre0 = *(const float4*)&W[(size_t)(k0 + br0) * N + colBase + bc0];
            bPre1 = *(const float4*)&W[(size_t)(k0 + br1) * N + colBase + bc1];
        }

        #pragma unroll
        for (int ks = 0; ks < 2; ks++) {
            int kb = ks * 8;
            unsigned af[2][4];
            #pragma unroll
            for (int mi = 0; mi < 2; mi++) {
                const unsigned* ap = &As[cur][(wm + mi * 16 + gid) * ASTR + kb + tig];
                af[mi][0] = ap[0];
                af[mi][1] = ap[8 * ASTR];
                af[mi][2] = ap[4];
                af[mi][3] = ap[8 * ASTR + 4];
            }
            unsigned bf[8][2];
            #pragma unroll
            for (int ni = 0; ni < 8; ni++) {
                const unsigned* bp = &Bs[cur][(kb + tig) * BSTR + wn + ni * 8 + gid];
                bf[ni][0] = bp[0];
                bf[ni][1] = bp[4 * BSTR];
            }
            #pragma unroll
            for (int mi = 0; mi < 2; mi++)
                #pragma unroll
                for (int ni = 0; ni < 8; ni++)
                    mma_tf32(c[mi][ni], af[mi], bf[ni]);
        }

        if (hasNext) {
            int nb = cur ^ 1;
            unsigned* p;
            p = &As[nb][ar0 * ASTR + ac0];
            p[0]=f2tf(aPre0.x); p[1]=f2tf(aPre0.y); p[2]=f2tf(aPre0.z); p[3]=f2tf(aPre0.w);
            p = &As[nb][ar1 * ASTR + ac1];
            p[0]=f2tf(aPre1.x); p[1]=f2tf(aPre1.y); p[2]=f2tf(aPre1.z); p[3]=f2tf(aPre1.w);
            p = &Bs[nb][br0 * BSTR + bc0];
            p[0]=f2tf(bPre0.x); p[1]=f2tf(bPre0.y); p[2]=f2tf(bPre0.z); p[3]=f2tf(bPre0.w);
            p = &Bs[nb][br1 * BSTR + bc1];
            p[0]=f2tf(bPre1.x); p[1]=f2tf(bPre1.y); p[2]=f2tf(bPre1.z); p[3]=f2tf(bPre1.w);
            __syncthreads();
        }
    }

    #pragma unroll
    for (int mi = 0; mi < 2; mi++) {
        size_t r0 = rowBase + wm + mi * 16 + gid;
        size_t r1 = r0 + 8;
        #pragma unroll
        for (int ni = 0; ni < 8; ni++) {
            size_t col = colBase + wn + ni * 8 + tig * 2;
            float b0 = bias[col], b1 = bias[col + 1];
            float v0 = (c[mi][ni][0] + b0) * scale;
            float v1 = (c[mi][ni][1] + b1) * scale;
            float v2 = (c[mi][ni][2] + b0) * scale;
            float v3 = (c[mi][ni][3] + b1) * scale;
            if (act == 1) {
                v0 = 0.5f * v0 * (1.0f + erff(v0 * 0.70710678f));
                v1 = 0.5f * v1 * (1.0f + erff(v1 * 0.70710678f));
                v2 = 0.5f * v2 * (1.0f + erff(v2 * 0.70710678f));
                v3 = 0.5f * v3 * (1.0f + erff(v3 * 0.70710678f));
            }
            *(float2*)&Co[r0 * N + col] = make_float2(v0, v1);
            *(float2*)&Co[r1 * N + col] = make_float2(v2, v3);
        }
    }
}

// ---------------- sliding-window attention, 16-query tiles ----------------
// grid = (S_/16, H_, B_), 256 threads, 3 CTAs/SM.
// smem (float units): qU 16x68 | kvU 64x68 | sc 16x772 | inv[16] | mv[64]
#define SCW2 772
#define AT_Q   0
#define AT_KV  1088
#define AT_SC  5440
#define AT_INV 17792
#define AT_MV  17808
#define AT_SMEM (17872 * 4)

__global__ __launch_bounds__(256, 3) void sw_attn_kernel(
        const float* __restrict__ q,
        const float* __restrict__ k,
        const float* __restrict__ v,
        const int* __restrict__ mask,
        float* __restrict__ ctx) {
    extern __shared__ float sm[];
    unsigned* qU  = (unsigned*)(sm + AT_Q);
    unsigned* kvU = (unsigned*)(sm + AT_KV);
    float* sc  = sm + AT_SC;
    float* inv = sm + AT_INV;
    float* mv  = sm + AT_MV;
    unsigned* scU = (unsigned*)sc;

    int tid = threadIdx.x;
    int lane = tid & 31, w = tid >> 5;
    int gid = lane >> 2, ti = lane & 3;
    int h = blockIdx.y, b = blockIdx.z;
    int qbase = blockIdx.x * 16;
    int n = qbase / C_;
    int cbase = qbase % C_;
    int j0 = (n - 1) * C_;
    int n0 = w * 8;

    // valid key-tile range for this 16-query band: [cbase, cbase + 2C + 15]
    int ktlo = cbase >> 6;
    int kthi = (cbase + 2 * C_ + 15) >> 6;
    int klo = ktlo * 64, khi = kthi * 64 + 63;

    // stage q (tf32) [q][d] : 16 rows x 64 d = 256 float4 chunks
    {
        int r = tid >> 4, c4 = (tid & 15) * 4;
        float4 qv = *(const float4*)&q[((size_t)(b * S_ + qbase + r)) * D_ + h * DH_ + c4];
        qU[r * 68 + c4 + 0] = f2tf(qv.x);
        qU[r * 68 + c4 + 1] = f2tf(qv.y);
        qU[r * 68 + c4 + 2] = f2tf(qv.z);
        qU[r * 68 + c4 + 3] = f2tf(qv.w);
    }
    __syncthreads();

    // hoist Q fragments
    unsigned aF[8][4];
    #pragma unroll
    for (int ks = 0; ks < 8; ks++) {
        const unsigned* ap = &qU[gid * 68 + ks * 8 + ti];
        aF[ks][0] = ap[0];
        aF[ks][1] = ap[8 * 68];
        aF[ks][2] = ap[4];
        aF[ks][3] = ap[8 * 68 + 4];
    }

    // ---- score phase ----
    for (int kt = ktlo; kt <= kthi; kt++) {
        __syncthreads();
        #pragma unroll
        for (int p = 0; p < 4; p++) {
            int s = tid + p * 256;
            int r = s >> 4, c4 = (s & 15) * 4;
            int j = j0 + kt * 64 + r;
            float4 kvv = make_float4(0.f, 0.f, 0.f, 0.f);
            if (j >= 0 && j < S_)
                kvv = *(const float4*)&k[((size_t)(b * S_ + j)) * D_ + h * DH_ + c4];
            unsigned* kp = &kvU[r * 68 + c4];
            kp[0] = f2tf(kvv.x); kp[1] = f2tf(kvv.y);
            kp[2] = f2tf(kvv.z); kp[3] = f2tf(kvv.w);
            if (c4 == 0)
                mv[r] = (j > 0 && j < S_ && mask[b * S_ + j] > 0) ? 1.0f : 0.0f;
        }
        __syncthreads();

        float cS[4] = {0.f, 0.f, 0.f, 0.f};
        #pragma unroll
        for (int ks = 0; ks < 8; ks++) {
            unsigned bb[2];
            bb[0] = kvU[(n0 + gid) * 68 + ks * 8 + ti];
            bb[1] = kvU[(n0 + gid) * 68 + ks * 8 + ti + 4];
            mma_tf32(cS, aF[ks], bb);
        }

        int kk0 = kt * 64 + n0 + 2 * ti;
        float valid0 = mv[n0 + 2 * ti], valid1 = mv[n0 + 2 * ti + 1];
        int r0 = gid, r1 = gid + 8;
        int cq0 = cbase + r0, cq1 = cbase + r1;
        bool ok00 = (valid0 > 0.5f) && (kk0 >= cq0) && (kk0 <= cq0 + 2 * C_);
        bool ok01 = (valid1 > 0.5f) && (kk0 + 1 >= cq0) && (kk0 + 1 <= cq0 + 2 * C_);
        bool ok10 = (valid0 > 0.5f) && (kk0 >= cq1) && (kk0 <= cq1 + 2 * C_);
        bool ok11 = (valid1 > 0.5f) && (kk0 + 1 >= cq1) && (kk0 + 1 <= cq1 + 2 * C_);
        sc[r0 * SCW2 + kk0]     = ok00 ? cS[0] : NEGV;
        sc[r0 * SCW2 + kk0 + 1] = ok01 ? cS[1] : NEGV;
        sc[r1 * SCW2 + kk0]     = ok10 ? cS[2] : NEGV;
        sc[r1 * SCW2 + kk0 + 1] = ok11 ? cS[3] : NEGV;
    }

    // global-token score (16 rows)
    if (tid < 16) {
        float acc = 0.0f;
        const float* k0p = k + ((size_t)(b * S_)) * D_ + h * DH_;
        #pragma unroll 8
        for (int d = 0; d < 64; d++)
            acc = fmaf(__uint_as_float(qU[tid * 68 + d]), k0p[d], acc);
        sc[tid * SCW2 + 3 * C_] = (mask[b * S_] > 0) ? acc : NEGV;
    }
    __syncthreads();

    // ---- softmax: warp w handles rows w and w+8, clipped range ----
    for (int rr = 0; rr < 2; rr++) {
        int qi = w + rr * 8;
        float* row = sc + qi * SCW2;
        float m = -INFINITY;
        for (int j = klo + lane; j <= khi; j += 32) m = fmaxf(m, row[j]);
        if (lane == 0) m = fmaxf(m, row[3 * C_]);
        m = warp_max(m);
        float ssum = 0.0f;
        for (int j = klo + lane; j <= khi; j += 32) {
            float e = __expf(row[j] - m);
            ssum += e;
            row[j] = __uint_as_float(f2tf(e));
        }
        if (lane == 0) {
            float e = __expf(row[3 * C_] - m);
            ssum += e;
            row[3 * C_] = e;   // keep fp32 (used as scalar)
        }
        ssum = warp_sum(ssum);
        if (lane == 0) inv[qi] = 1.0f / ssum;
    }

    // ---- PV phase ----
    float cO[4] = {0.f, 0.f, 0.f, 0.f};
    for (int kt = ktlo; kt <= kthi; kt++) {
        __syncthreads();
        #pragma unroll
        for (int p = 0; p < 4; p++) {
            int s = tid + p * 256;
            int r = s >> 4, c4 = (s & 15) * 4;
            int j = j0 + kt * 64 + r;
            float4 vv = make_float4(0.f, 0.f, 0.f, 0.f);
            if (j >= 0 && j < S_)
                vv = *(const float4*)&v[((size_t)(b * S_ + j)) * D_ + h * DH_ + c4];
            kvU[(c4 + 0) * 68 + (r ^ ((c4 + 0) >> 3))] = f2tf(vv.x);
            kvU[(c4 + 1) * 68 + (r ^ ((c4 + 1) >> 3))] = f2tf(vv.y);
            kvU[(c4 + 2) * 68 + (r ^ ((c4 + 2) >> 3))] = f2tf(vv.z);
            kvU[(c4 + 3) * 68 + (r ^ ((c4 + 3) >> 3))] = f2tf(vv.w);
        }
        __syncthreads();

        #pragma unroll
        for (int ks = 0; ks < 8; ks++) {
            unsigned bb[2];
            int drow = n0 + gid;
            bb[0] = kvU[drow * 68 + ((ks * 8 + ti) ^ w)];
            bb[1] = kvU[drow * 68 + ((ks * 8 + ti + 4) ^ w)];
            unsigned aa[4];
            const unsigned* pp = &scU[gid * SCW2 + kt * 64 + ks * 8 + ti];
            aa[0] = pp[0];
            aa[1] = pp[8 * SCW2];
            aa[2] = pp[4];
            aa[3] = pp[8 * SCW2 + 4];
            mma_tf32(cO, aa, bb);
        }
    }

    // add global-token contribution and write
    {
        const float* v0p = v + ((size_t)(b * S_)) * D_ + h * DH_;
        int d0 = n0 + 2 * ti;
        float gv0 = v0p[d0], gv1 = v0p[d0 + 1];
        int r0 = gid, r1 = gid + 8;
        float g0 = sc[r0 * SCW2 + 3 * C_], g1 = sc[r1 * SCW2 + 3 * C_];
        float i0 = inv[r0], i1 = inv[r1];
        float2 o0 = make_float2((cO[0] + g0 * gv0) * i0,
                                (cO[1] + g0 * gv1) * i0);
        float2 o1 = make_float2((cO[2] + g1 * gv0) * i1,
                                (cO[3] + g1 * gv1) * i1);
        *(float2*)&ctx[((size_t)(b * S_ + qbase + r0)) * D_ + h * DH_ + d0] = o0;
        *(float2*)&ctx[((size_t)(b * S_ + qbase + r1)) * D_ + h * DH_ + d0] = o1;
    }
}

// ---------------- full attention for query row 0 ----------------
__global__ void global_attn_kernel(const float* __restrict__ q,
                                   const float* __restrict__ k,
                                   const float* __restrict__ v,
                                   const int* __restrict__ mask,
                                   float* __restrict__ ctx) {
    __shared__ float qs[64];
    __shared__ float sc[S_];
    __shared__ float red[32];
    __shared__ float cpart[256];
    int h = blockIdx.x, b = blockIdx.y;
    int tid = threadIdx.x;
    const float* qp = q + ((size_t)(b * S_)) * D_ + h * DH_;
    if (tid < 16) ((float4*)qs)[tid] = ((const float4*)qp)[tid];
    __syncthreads();

    for (int j = tid; j < S_; j += 256) {
        float s = NEGV;
        if (mask[b * S_ + j] > 0) {
            const float4* kp = (const float4*)(k + ((size_t)(b * S_ + j)) * D_ + h * DH_);
            float acc = 0.0f;
            #pragma unroll
            for (int d4 = 0; d4 < 16; d4++) {
                float4 kvv = kp[d4];
                float4 qv = ((const float4*)qs)[d4];
                acc += kvv.x * qv.x + kvv.y * qv.y + kvv.z * qv.z + kvv.w * qv.w;
            }
            s = acc;
        }
        sc[j] = s;
    }
    __syncthreads();

    float m = -INFINITY;
    for (int j = tid; j < S_; j += 256) m = fmaxf(m, sc[j]);
    m = block_max(m, red);
    float lsum = 0.0f;
    for (int j = tid; j < S_; j += 256) {
        float e = __expf(sc[j] - m);
        sc[j] = e;
        lsum += e;
    }
    float sum = block_sum(lsum, red);
    float inv = 1.0f / sum;

    int d = tid & 63, part = tid >> 6;
    float accum = 0.0f;
    for (int j = part; j < S_; j += 4)
        accum += sc[j] * v[((size_t)(b * S_ + j)) * D_ + h * DH_ + d];
    cpart[tid] = accum;
    __syncthreads();
    if (part == 0)
        ctx[((size_t)(b * S_)) * D_ + h * DH_ + d] =
            (cpart[d] + cpart[64 + d] + cpart[128 + d] + cpart[192 + d]) * inv;
}

// ---------------- classifier head ----------------
__global__ void cls_kernel(const float* __restrict__ h,
                           const float* __restrict__ W,
                           const float* __restrict__ bias,
                           float* __restrict__ out) {
    int w = threadIdx.x >> 5, lane = threadIdx.x & 31;
    if (w < B_ * 3) {
        int b = w / 3, c = w % 3;
        float acc = 0.0f;
        for (int kx = lane; kx < D_; kx += 32)
            acc += h[((size_t)(b * S_)) * D_ + kx] * W[kx * 3 + c];
        acc = warp_sum(acc);
        if (lane == 0) out[b * 3 + c] = acc + bias[c];
    }
}

// ---------------- launch ----------------
extern "C" void kernel_launch(void* const* d_in, const int* in_sizes, int n_in,
                              void* d_out, int out_size) {
    const int*   ids      = (const int*)d_in[0];
    const int*   mask     = (const int*)d_in[1];
    const float* emb_tok  = (const float*)d_in[2];
    const float* emb_pos  = (const float*)d_in[3];
    const float* emb_ln_g = (const float*)d_in[4];
    const float* emb_ln_b = (const float*)d_in[5];
    const float* Wq = (const float*)d_in[6];
    const float* bq = (const float*)d_in[7];
    const float* Wk = (const float*)d_in[8];
    const float* bk = (const float*)d_in[9];
    const float* Wv = (const float*)d_in[10];
    const float* bv = (const float*)d_in[11];
    const float* Wo = (const float*)d_in[12];
    const float* bo = (const float*)d_in[13];
    const float* ln1_g = (const float*)d_in[14];
    const float* ln1_b = (const float*)d_in[15];
    const float* W1 = (const float*)d_in[16];
    const float* b1 = (const float*)d_in[17];
    const float* W2 = (const float*)d_in[18];
    const float* b2 = (const float*)d_in[19];
    const float* ln2_g = (const float*)d_in[20];
    const float* ln2_b = (const float*)d_in[21];
    const float* clsW = (const float*)d_in[22];
    const float* clsb = (const float*)d_in[23];

    float *h, *q, *k, *v, *ctx, *t, *f;
    cudaGetSymbolAddress((void**)&h,   g_h);
    cudaGetSymbolAddress((void**)&q,   g_q);
    cudaGetSymbolAddress((void**)&k,   g_k);
    cudaGetSymbolAddress((void**)&v,   g_v);
    cudaGetSymbolAddress((void**)&ctx, g_ctx);
    cudaGetSymbolAddress((void**)&t,   g_t);
    cudaGetSymbolAddress((void**)&f,   g_f);

    static int attr_done = 0;
    if (!attr_done) {
        cudaFuncSetAttribute(sw_attn_kernel,
                             cudaFuncAttributeMaxDynamicSharedMemorySize, AT_SMEM);
        attr_done = 1;
    }

    embed_ln_kernel<<<M_, 256>>>(ids, emb_tok, emb_pos, emb_ln_g, emb_ln_b, h);

    for (int l = 0; l < L_; l++) {
        const float* Wql = Wq + (size_t)l * D_ * D_;
        const float* Wkl = Wk + (size_t)l * D_ * D_;
        const float* Wvl = Wv + (size_t)l * D_ * D_;
        const float* Wol = Wo + (size_t)l * D_ * D_;
        const float* W1l = W1 + (size_t)l * D_ * F_;
        const float* W2l = W2 + (size_t)l * F_ * D_;

        dim3 gQKV(D_ / TBN, M_ / TBM, 3);
        dim3 gD(D_ / TBN, M_ / TBM, 1);
        dim3 gF(F_ / TBN, M_ / TBM, 1);

        // fused Q,K,V projections: one launch, 3x CTAs (better wave packing)
        gemm_tf32_kernel<<<gQKV, 256>>>(h,
            Wql, Wkl, Wvl,
            bq + l * D_, bk + l * D_, bv + l * D_,
            q, k, v,
            M_, D_, D_, 0, 0.125f, 1.0f, 1.0f);

        sw_attn_kernel<<<dim3(S_ / 16, H_, B_), 256, AT_SMEM>>>(q, k, v, mask, ctx);
        global_attn_kernel<<<dim3(H_, B_), 256>>>(q, k, v, mask, ctx);

        gemm_tf32_kernel<<<gD, 256>>>(ctx,
            Wol, Wol, Wol, bo + l * D_, bo + l * D_, bo + l * D_,
            t, t, t, M_, D_, D_, 0, 1.0f, 1.0f, 1.0f);
        add_ln_kernel<<<M_, 256>>>(h, t, ln1_g + l * D_, ln1_b + l * D_, h);

        gemm_tf32_kernel<<<gF, 256>>>(h,
            W1l, W1l, W1l, b1 + l * F_, b1 + l * F_, b1 + l * F_,
            f, f, f, M_, F_, D_, 1, 1.0f, 1.0f, 1.0f);
        gemm_tf32_kernel<<<gD, 256>>>(f,
            W2l, W2l, W2l, b2 + l * D_, b2 + l * D_, b2 + l * D_,
            t, t, t, M_, D_, F_, 0, 1.0f, 1.0f, 1.0f);
        add_ln_kernel<<<M_, 256>>>(h, t, ln2_g + l * D_, ln2_b + l * D_, h);
    }

    cls_kernel<<<1, 256>>>(h, clsW, clsb, (float*)d_out);
}

// round 13
// speedup vs baseline: 1.6986x; 1.0649x over previous
#include <cuda_runtime.h>
#include <math.h>

// ---------------- problem constants ----------------
#define B_  2
#define S_  4096
#define D_  768
#define H_  12
#define DH_ 64
#define L_  2
#define F_  3072
#define C_  256
#define M_  (B_*S_)
#define NEGV (-1000000000.0f)
#define GNS 32            // global-attn split chunks
#define GCK 128           // keys per chunk

// ---------------- scratch ----------------
__device__ float g_h  [M_ * D_];
__device__ float g_q  [M_ * D_];
__device__ float g_k  [M_ * D_];
__device__ float g_v  [M_ * D_];
__device__ float g_ctx[M_ * D_];
__device__ float g_t  [M_ * D_];
__device__ float g_f  [M_ * F_];
__device__ float g_gp [B_ * H_ * GNS * 66];   // per-chunk partials: 64 o + m + s

// ---------------- helpers ----------------
__device__ __forceinline__ float warp_sum(float v) {
    #pragma unroll
    for (int o = 16; o; o >>= 1) v += __shfl_xor_sync(0xffffffffu, v, o);
    return v;
}
__device__ __forceinline__ float warp_max(float v) {
    #pragma unroll
    for (int o = 16; o; o >>= 1) v = fmaxf(v, __shfl_xor_sync(0xffffffffu, v, o));
    return v;
}
__device__ float block_sum(float v, float* red) {
    int lane = threadIdx.x & 31, w = threadIdx.x >> 5;
    v = warp_sum(v);
    __syncthreads();
    if (lane == 0) red[w] = v;
    __syncthreads();
    int nw = (blockDim.x + 31) >> 5;
    float r = (threadIdx.x < nw) ? red[threadIdx.x] : 0.0f;
    if (w == 0) { r = warp_sum(r); if (lane == 0) red[0] = r; }
    __syncthreads();
    return red[0];
}
__device__ float block_max(float v, float* red) {
    int lane = threadIdx.x & 31, w = threadIdx.x >> 5;
    v = warp_max(v);
    __syncthreads();
    if (lane == 0) red[w] = v;
    __syncthreads();
    int nw = (blockDim.x + 31) >> 5;
    float r = (threadIdx.x < nw) ? red[threadIdx.x] : -INFINITY;
    if (w == 0) { r = warp_max(r); if (lane == 0) red[0] = r; }
    __syncthreads();
    return red[0];
}

__device__ __forceinline__ unsigned f2tf(float v) {
    unsigned r; asm("cvt.rna.tf32.f32 %0, %1;" : "=r"(r) : "f"(v)); return r;
}
__device__ __forceinline__ void mma_tf32(float* c, const unsigned* a, const unsigned* b) {
    asm volatile(
        "mma.sync.aligned.m16n8k8.row.col.f32.tf32.tf32.f32 "
        "{%0,%1,%2,%3},{%4,%5,%6,%7},{%8,%9},{%0,%1,%2,%3};\n"
        : "+f"(c[0]), "+f"(c[1]), "+f"(c[2]), "+f"(c[3])
        : "r"(a[0]), "r"(a[1]), "r"(a[2]), "r"(a[3]), "r"(b[0]), "r"(b[1]));
}

// ---------------- embedding + layernorm ----------------
__global__ void embed_ln_kernel(const int* __restrict__ ids,
                                const float* __restrict__ tok,
                                const float* __restrict__ pos,
                                const float* __restrict__ g,
                                const float* __restrict__ be,
                                float* __restrict__ out) {
    __shared__ float red[32];
    int row = blockIdx.x;
    int s = row % S_;
    int id = ids[row];
    const float* tp = tok + (size_t)id * D_;
    const float* pp = pos + (size_t)s  * D_;
    float vals[3]; float lsum = 0.0f;
    #pragma unroll
    for (int i = 0; i < 3; i++) {
        int c = threadIdx.x + i * 256;
        vals[i] = tp[c] + pp[c];
        lsum += vals[i];
    }
    float mean = block_sum(lsum, red) * (1.0f / D_);
    float lv = 0.0f;
    #pragma unroll
    for (int i = 0; i < 3; i++) { float d = vals[i] - mean; lv += d * d; }
    float var = block_sum(lv, red) * (1.0f / D_);
    float inv = rsqrtf(var + 1e-5f);
    float* op = out + (size_t)row * D_;
    #pragma unroll
    for (int i = 0; i < 3; i++) {
        int c = threadIdx.x + i * 256;
        op[c] = (vals[i] - mean) * inv * g[c] + be[c];
    }
}

// ---------------- residual add + layernorm ----------------
__global__ void add_ln_kernel(const float* __restrict__ x,
                              const float* __restrict__ r,
                              const float* __restrict__ g,
                              const float* __restrict__ be,
                              float* __restrict__ out) {
    __shared__ float red[32];
    int row = blockIdx.x;
    const float* xp = x + (size_t)row * D_;
    const float* rp = r + (size_t)row * D_;
    float vals[3]; float lsum = 0.0f;
    #pragma unroll
    for (int i = 0; i < 3; i++) {
        int c = threadIdx.x + i * 256;
        vals[i] = xp[c] + rp[c];
        lsum += vals[i];
    }
    float mean = block_sum(lsum, red) * (1.0f / D_);
    float lv = 0.0f;
    #pragma unroll
    for (int i = 0; i < 3; i++) { float d = vals[i] - mean; lv += d * d; }
    float var = block_sum(lv, red) * (1.0f / D_);
    float inv = rsqrtf(var + 1e-5f);
    float* op = out + (size_t)row * D_;
    #pragma unroll
    for (int i = 0; i < 3; i++) {
        int c = threadIdx.x + i * 256;
        op[c] = (vals[i] - mean) * inv * g[c] + be[c];
    }
}

// ---------------- tf32 mma GEMM (R3 layout; cvt at smem store) ----------------
#define TBM 128
#define TBN 128
#define TBK 16
#define ASTR 20
#define BSTR 132

__global__ __launch_bounds__(256) void gemm_tf32_kernel(
        const float* __restrict__ A,
        const float* __restrict__ W0, const float* __restrict__ W1p,
        const float* __restrict__ W2p,
        const float* __restrict__ bi0, const float* __restrict__ bi1,
        const float* __restrict__ bi2,
        float* __restrict__ C0, float* __restrict__ C1, float* __restrict__ C2,
        int M, int N, int K, int act, float s0, float s1, float s2) {
    __shared__ unsigned As[2][TBM * ASTR];
    __shared__ unsigned Bs[2][TBK * BSTR];

    int z = blockIdx.z;
    const float* W    = (z == 0) ? W0  : (z == 1) ? W1p : W2p;
    const float* bias = (z == 0) ? bi0 : (z == 1) ? bi1 : bi2;
    float*       Co   = (z == 0) ? C0  : (z == 1) ? C1  : C2;
    float scale       = (z == 0) ? s0  : (z == 1) ? s1  : s2;

    int tid = threadIdx.x;
    int lane = tid & 31, wid = tid >> 5;
    int wm = (wid & 3) * 32;
    int wn = (wid >> 2) * 64;
    int gid = lane >> 2, tig = lane & 3;
    size_t rowBase = (size_t)blockIdx.y * TBM;
    size_t colBase = (size_t)blockIdx.x * TBN;

    int s0i = tid, s1i = tid + 256;
    int ar0 = s0i >> 2, ac0 = (s0i & 3) * 4;
    int ar1 = s1i >> 2, ac1 = (s1i & 3) * 4;
    int br0 = s0i >> 5, bc0 = (s0i & 31) * 4;
    int br1 = s1i >> 5, bc1 = (s1i & 31) * 4;

    float c[2][8][4];
    #pragma unroll
    for (int mi = 0; mi < 2; mi++)
        #pragma unroll
        for (int ni = 0; ni < 8; ni++)
            #pragma unroll
            for (int q = 0; q < 4; q++) c[mi][ni][q] = 0.0f;

    int ntiles = K / TBK;

    float4 aPre0, aPre1, bPre0, bPre1;
    aPre0 = *(const float4*)&A[(rowBase + ar0) * K + ac0];
    aPre1 = *(const float4*)&A[(rowBase + ar1) * K + ac1];
    bPre0 = *(const float4*)&W[(size_t)br0 * N + colBase + bc0];
    bPre1 = *(const float4*)&W[(size_t)br1 * N + colBase + bc1];
    {
        unsigned* p;
        p = &As[0][ar0 * ASTR + ac0];
        p[0]=f2tf(aPre0.x); p[1]=f2tf(aPre0.y); p[2]=f2tf(aPre0.z); p[3]=f2tf(aPre0.w);
        p = &As[0][ar1 * ASTR + ac1];
        p[0]=f2tf(aPre1.x); p[1]=f2tf(aPre1.y); p[2]=f2tf(aPre1.z); p[3]=f2tf(aPre1.w);
        p = &Bs[0][br0 * BSTR + bc0];
        p[0]=f2tf(bPre0.x); p[1]=f2tf(bPre0.y); p[2]=f2tf(bPre0.z); p[3]=f2tf(bPre0.w);
        p = &Bs[0][br1 * BSTR + bc1];
        p[0]=f2tf(bPre1.x); p[1]=f2tf(bPre1.y); p[2]=f2tf(bPre1.z); p[3]=f2tf(bPre1.w);
    }
    __syncthreads();

    for (int kt = 0; kt < ntiles; kt++) {
        int cur = kt & 1;
        bool hasNext = (kt + 1) < ntiles;
        if (hasNext) {
            int k0 = (kt + 1) * TBK;
            aPre0 = *(const float4*)&A[(rowBase + ar0) * K + k0 + ac0];
            aPre1 = *(const float4*)&A[(rowBase + ar1) * K + k0 + ac1];
            bPre0 = *(const float4*)&W[(size_t)(k0 + br0) * N + colBase + bc0];
            bPre1 = *(const float4*)&W[(size_t)(k0 + br1) * N + colBase + bc1];
        }

        #pragma unroll
        for (int ks = 0; ks < 2; ks++) {
            int kb = ks * 8;
            unsigned af[2][4];
            #pragma unroll
            for (int mi = 0; mi < 2; mi++) {
                const unsigned* ap = &As[cur][(wm + mi * 16 + gid) * ASTR + kb + tig];
                af[mi][0] = ap[0];
                af[mi][1] = ap[8 * ASTR];
                af[mi][2] = ap[4];
                af[mi][3] = ap[8 * ASTR + 4];
            }
            unsigned bf[8][2];
            #pragma unroll
            for (int ni = 0; ni < 8; ni++) {
                const unsigned* bp = &Bs[cur][(kb + tig) * BSTR + wn + ni * 8 + gid];
                bf[ni][0] = bp[0];
                bf[ni][1] = bp[4 * BSTR];
            }
            #pragma unroll
            for (int mi = 0; mi < 2; mi++)
                #pragma unroll
                for (int ni = 0; ni < 8; ni++)
                    mma_tf32(c[mi][ni], af[mi], bf[ni]);
        }

        if (hasNext) {
            int nb = cur ^ 1;
            unsigned* p;
            p = &As[nb][ar0 * ASTR + ac0];
            p[0]=f2tf(aPre0.x); p[1]=f2tf(aPre0.y); p[2]=f2tf(aPre0.z); p[3]=f2tf(aPre0.w);
            p = &As[nb][ar1 * ASTR + ac1];
            p[0]=f2tf(aPre1.x); p[1]=f2tf(aPre1.y); p[2]=f2tf(aPre1.z); p[3]=f2tf(aPre1.w);
            p = &Bs[nb][br0 * BSTR + bc0];
            p[0]=f2tf(bPre0.x); p[1]=f2tf(bPre0.y); p[2]=f2tf(bPre0.z); p[3]=f2tf(bPre0.w);
            p = &Bs[nb][br1 * BSTR + bc1];
            p[0]=f2tf(bPre1.x); p[1]=f2tf(bPre1.y); p[2]=f2tf(bPre1.z); p[3]=f2tf(bPre1.w);
            __syncthreads();
        }
    }

    #pragma unroll
    for (int mi = 0; mi < 2; mi++) {
        size_t r0 = rowBase + wm + mi * 16 + gid;
        size_t r1 = r0 + 8;
        #pragma unroll
        for (int ni = 0; ni < 8; ni++) {
            size_t col = colBase + wn + ni * 8 + tig * 2;
            float b0 = bias[col], b1 = bias[col + 1];
            float v0 = (c[mi][ni][0] + b0) * scale;
            float v1 = (c[mi][ni][1] + b1) * scale;
            float v2 = (c[mi][ni][2] + b0) * scale;
            float v3 = (c[mi][ni][3] + b1) * scale;
            if (act == 1) {
                v0 = 0.5f * v0 * (1.0f + erff(v0 * 0.70710678f));
                v1 = 0.5f * v1 * (1.0f + erff(v1 * 0.70710678f));
                v2 = 0.5f * v2 * (1.0f + erff(v2 * 0.70710678f));
                v3 = 0.5f * v3 * (1.0f + erff(v3 * 0.70710678f));
            }
            *(float2*)&Co[r0 * N + col] = make_float2(v0, v1);
            *(float2*)&Co[r1 * N + col] = make_float2(v2, v3);
        }
    }
}

// ---------------- sliding-window attention, 16-query tiles ----------------
#define SCW2 772
#define AT_Q   0
#define AT_KV  1088
#define AT_SC  5440
#define AT_INV 17792
#define AT_MV  17808
#define AT_SMEM (17872 * 4)

__global__ __launch_bounds__(256, 3) void sw_attn_kernel(
        const float* __restrict__ q,
        const float* __restrict__ k,
        const float* __restrict__ v,
        const int* __restrict__ mask,
        float* __restrict__ ctx) {
    extern __shared__ float sm[];
    unsigned* qU  = (unsigned*)(sm + AT_Q);
    unsigned* kvU = (unsigned*)(sm + AT_KV);
    float* sc  = sm + AT_SC;
    float* inv = sm + AT_INV;
    float* mv  = sm + AT_MV;
    unsigned* scU = (unsigned*)sc;

    int tid = threadIdx.x;
    int lane = tid & 31, w = tid >> 5;
    int gid = lane >> 2, ti = lane & 3;
    int h = blockIdx.y, b = blockIdx.z;
    int qbase = blockIdx.x * 16;
    int n = qbase / C_;
    int cbase = qbase % C_;
    int j0 = (n - 1) * C_;
    int n0 = w * 8;

    int ktlo = cbase >> 6;
    int kthi = (cbase + 2 * C_ + 15) >> 6;
    int klo = ktlo * 64, khi = kthi * 64 + 63;

    {
        int r = tid >> 4, c4 = (tid & 15) * 4;
        float4 qv = *(const float4*)&q[((size_t)(b * S_ + qbase + r)) * D_ + h * DH_ + c4];
        qU[r * 68 + c4 + 0] = f2tf(qv.x);
        qU[r * 68 + c4 + 1] = f2tf(qv.y);
        qU[r * 68 + c4 + 2] = f2tf(qv.z);
        qU[r * 68 + c4 + 3] = f2tf(qv.w);
    }
    __syncthreads();

    unsigned aF[8][4];
    #pragma unroll
    for (int ks = 0; ks < 8; ks++) {
        const unsigned* ap = &qU[gid * 68 + ks * 8 + ti];
        aF[ks][0] = ap[0];
        aF[ks][1] = ap[8 * 68];
        aF[ks][2] = ap[4];
        aF[ks][3] = ap[8 * 68 + 4];
    }

    for (int kt = ktlo; kt <= kthi; kt++) {
        __syncthreads();
        #pragma unroll
        for (int p = 0; p < 4; p++) {
            int s = tid + p * 256;
            int r = s >> 4, c4 = (s & 15) * 4;
            int j = j0 + kt * 64 + r;
            float4 kvv = make_float4(0.f, 0.f, 0.f, 0.f);
            if (j >= 0 && j < S_)
                kvv = *(const float4*)&k[((size_t)(b * S_ + j)) * D_ + h * DH_ + c4];
            unsigned* kp = &kvU[r * 68 + c4];
            kp[0] = f2tf(kvv.x); kp[1] = f2tf(kvv.y);
            kp[2] = f2tf(kvv.z); kp[3] = f2tf(kvv.w);
            if (c4 == 0)
                mv[r] = (j > 0 && j < S_ && mask[b * S_ + j] > 0) ? 1.0f : 0.0f;
        }
        __syncthreads();

        float cS[4] = {0.f, 0.f, 0.f, 0.f};
        #pragma unroll
        for (int ks = 0; ks < 8; ks++) {
            unsigned bb[2];
            bb[0] = kvU[(n0 + gid) * 68 + ks * 8 + ti];
            bb[1] = kvU[(n0 + gid) * 68 + ks * 8 + ti + 4];
            mma_tf32(cS, aF[ks], bb);
        }

        int kk0 = kt * 64 + n0 + 2 * ti;
        float valid0 = mv[n0 + 2 * ti], valid1 = mv[n0 + 2 * ti + 1];
        int r0 = gid, r1 = gid + 8;
        int cq0 = cbase + r0, cq1 = cbase + r1;
        bool ok00 = (valid0 > 0.5f) && (kk0 >= cq0) && (kk0 <= cq0 + 2 * C_);
        bool ok01 = (valid1 > 0.5f) && (kk0 + 1 >= cq0) && (kk0 + 1 <= cq0 + 2 * C_);
        bool ok10 = (valid0 > 0.5f) && (kk0 >= cq1) && (kk0 <= cq1 + 2 * C_);
        bool ok11 = (valid1 > 0.5f) && (kk0 + 1 >= cq1) && (kk0 + 1 <= cq1 + 2 * C_);
        sc[r0 * SCW2 + kk0]     = ok00 ? cS[0] : NEGV;
        sc[r0 * SCW2 + kk0 + 1] = ok01 ? cS[1] : NEGV;
        sc[r1 * SCW2 + kk0]     = ok10 ? cS[2] : NEGV;
        sc[r1 * SCW2 + kk0 + 1] = ok11 ? cS[3] : NEGV;
    }

    if (tid < 16) {
        float acc = 0.0f;
        const float* k0p = k + ((size_t)(b * S_)) * D_ + h * DH_;
        #pragma unroll 8
        for (int d = 0; d < 64; d++)
            acc = fmaf(__uint_as_float(qU[tid * 68 + d]), k0p[d], acc);
        sc[tid * SCW2 + 3 * C_] = (mask[b * S_] > 0) ? acc : NEGV;
    }
    __syncthreads();

    for (int rr = 0; rr < 2; rr++) {
        int qi = w + rr * 8;
        float* row = sc + qi * SCW2;
        float m = -INFINITY;
        for (int j = klo + lane; j <= khi; j += 32) m = fmaxf(m, row[j]);
        if (lane == 0) m = fmaxf(m, row[3 * C_]);
        m = warp_max(m);
        float ssum = 0.0f;
        for (int j = klo + lane; j <= khi; j += 32) {
            float e = __expf(row[j] - m);
            ssum += e;
            row[j] = __uint_as_float(f2tf(e));
        }
        if (lane == 0) {
            float e = __expf(row[3 * C_] - m);
            ssum += e;
            row[3 * C_] = e;
        }
        ssum = warp_sum(ssum);
        if (lane == 0) inv[qi] = 1.0f / ssum;
    }

    float cO[4] = {0.f, 0.f, 0.f, 0.f};
    for (int kt = ktlo; kt <= kthi; kt++) {
        __syncthreads();
        #pragma unroll
        for (int p = 0; p < 4; p++) {
            int s = tid + p * 256;
            int r = s >> 4, c4 = (s & 15) * 4;
            int j = j0 + kt * 64 + r;
            float4 vv = make_float4(0.f, 0.f, 0.f, 0.f);
            if (j >= 0 && j < S_)
                vv = *(const float4*)&v[((size_t)(b * S_ + j)) * D_ + h * DH_ + c4];
            kvU[(c4 + 0) * 68 + (r ^ ((c4 + 0) >> 3))] = f2tf(vv.x);
            kvU[(c4 + 1) * 68 + (r ^ ((c4 + 1) >> 3))] = f2tf(vv.y);
            kvU[(c4 + 2) * 68 + (r ^ ((c4 + 2) >> 3))] = f2tf(vv.z);
            kvU[(c4 + 3) * 68 + (r ^ ((c4 + 3) >> 3))] = f2tf(vv.w);
        }
        __syncthreads();

        #pragma unroll
        for (int ks = 0; ks < 8; ks++) {
            unsigned bb[2];
            int drow = n0 + gid;
            bb[0] = kvU[drow * 68 + ((ks * 8 + ti) ^ w)];
            bb[1] = kvU[drow * 68 + ((ks * 8 + ti + 4) ^ w)];
            unsigned aa[4];
            const unsigned* pp = &scU[gid * SCW2 + kt * 64 + ks * 8 + ti];
            aa[0] = pp[0];
            aa[1] = pp[8 * SCW2];
            aa[2] = pp[4];
            aa[3] = pp[8 * SCW2 + 4];
            mma_tf32(cO, aa, bb);
        }
    }

    {
        const float* v0p = v + ((size_t)(b * S_)) * D_ + h * DH_;
        int d0 = n0 + 2 * ti;
        float gv0 = v0p[d0], gv1 = v0p[d0 + 1];
        int r0 = gid, r1 = gid + 8;
        float g0 = sc[r0 * SCW2 + 3 * C_], g1 = sc[r1 * SCW2 + 3 * C_];
        float i0 = inv[r0], i1 = inv[r1];
        float2 o0 = make_float2((cO[0] + g0 * gv0) * i0,
                                (cO[1] + g0 * gv1) * i0);
        float2 o1 = make_float2((cO[2] + g1 * gv0) * i1,
                                (cO[3] + g1 * gv1) * i1);
        *(float2*)&ctx[((size_t)(b * S_ + qbase + r0)) * D_ + h * DH_ + d0] = o0;
        *(float2*)&ctx[((size_t)(b * S_ + qbase + r1)) * D_ + h * DH_ + d0] = o1;
    }
}

// ---------------- global-row attention, split-KV ----------------
// Stage 1: grid (H_, B_, GNS), 128 threads; each block = 128 keys.
__global__ __launch_bounds__(128) void gattn_part_kernel(
        const float* __restrict__ q,
        const float* __restrict__ k,
        const float* __restrict__ v,
        const int* __restrict__ mask,
        float* __restrict__ part) {
    __shared__ float qs[64];
    __shared__ float red[32];
    __shared__ float ps[GCK];
    int h = blockIdx.x, b = blockIdx.y, ch = blockIdx.z;
    int tid = threadIdx.x;
    const float* qp = q + ((size_t)(b * S_)) * D_ + h * DH_;
    if (tid < 16) ((float4*)qs)[tid] = ((const float4*)qp)[tid];
    __syncthreads();

    int j = ch * GCK + tid;
    float s = NEGV;
    if (mask[b * S_ + j] > 0) {
        const float4* kp = (const float4*)(k + ((size_t)(b * S_ + j)) * D_ + h * DH_);
        float acc = 0.0f;
        #pragma unroll
        for (int d4 = 0; d4 < 16; d4++) {
            float4 kv = kp[d4];
            float4 qv = ((const float4*)qs)[d4];
            acc += kv.x * qv.x + kv.y * qv.y + kv.z * qv.z + kv.w * qv.w;
        }
        s = acc;
    }
    float m = block_max(s, red);
    float e = __expf(s - m);
    float ssum = block_sum(e, red);
    ps[tid] = e;
    __syncthreads();

    float* op = part + ((size_t)(b * H_ + h) * GNS + ch) * 66;
    if (tid < 64) {
        float acc = 0.0f;
        const float* vp = v + ((size_t)(b * S_ + ch * GCK)) * D_ + h * DH_ + tid;
        #pragma unroll 4
        for (int kk = 0; kk < GCK; kk++)
            acc = fmaf(ps[kk], vp[(size_t)kk * D_], acc);
        op[tid] = acc;
    } else if (tid == 64) {
        op[64] = m;
        op[65] = ssum;
    }
}

// Stage 2: grid (H_, B_), 64 threads. Overwrites ctx row 0.
__global__ __launch_bounds__(64) void gattn_comb_kernel(
        const float* __restrict__ part,
        float* __restrict__ ctx) {
    int h = blockIdx.x, b = blockIdx.y;
    int tid = threadIdx.x;
    const float* pp = part + ((size_t)(b * H_ + h) * GNS) * 66;
    float M = -INFINITY;
    #pragma unroll
    for (int i = 0; i < GNS; i++) M = fmaxf(M, pp[i * 66 + 64]);
    float S = 0.0f, acc = 0.0f;
    #pragma unroll
    for (int i = 0; i < GNS; i++) {
        float wgt = __expf(pp[i * 66 + 64] - M);
        S += pp[i * 66 + 65] * wgt;
        acc += pp[i * 66 + tid] * wgt;
    }
    ctx[((size_t)(b * S_)) * D_ + h * DH_ + tid] = acc / S;
}

// ---------------- classifier head ----------------
__global__ void cls_kernel(const float* __restrict__ h,
                           const float* __restrict__ W,
                           const float* __restrict__ bias,
                           float* __restrict__ out) {
    int w = threadIdx.x >> 5, lane = threadIdx.x & 31;
    if (w < B_ * 3) {
        int b = w / 3, c = w % 3;
        float acc = 0.0f;
        for (int kx = lane; kx < D_; kx += 32)
            acc += h[((size_t)(b * S_)) * D_ + kx] * W[kx * 3 + c];
        acc = warp_sum(acc);
        if (lane == 0) out[b * 3 + c] = acc + bias[c];
    }
}

// ---------------- launch ----------------
extern "C" void kernel_launch(void* const* d_in, const int* in_sizes, int n_in,
                              void* d_out, int out_size) {
    const int*   ids      = (const int*)d_in[0];
    const int*   mask     = (const int*)d_in[1];
    const float* emb_tok  = (const float*)d_in[2];
    const float* emb_pos  = (const float*)d_in[3];
    const float* emb_ln_g = (const float*)d_in[4];
    const float* emb_ln_b = (const float*)d_in[5];
    const float* Wq = (const float*)d_in[6];
    const float* bq = (const float*)d_in[7];
    const float* Wk = (const float*)d_in[8];
    const float* bk = (const float*)d_in[9];
    const float* Wv = (const float*)d_in[10];
    const float* bv = (const float*)d_in[11];
    const float* Wo = (const float*)d_in[12];
    const float* bo = (const float*)d_in[13];
    const float* ln1_g = (const float*)d_in[14];
    const float* ln1_b = (const float*)d_in[15];
    const float* W1 = (const float*)d_in[16];
    const float* b1 = (const float*)d_in[17];
    const float* W2 = (const float*)d_in[18];
    const float* b2 = (const float*)d_in[19];
    const float* ln2_g = (const float*)d_in[20];
    const float* ln2_b = (const float*)d_in[21];
    const float* clsW = (const float*)d_in[22];
    const float* clsb = (const float*)d_in[23];

    float *h, *q, *k, *v, *ctx, *t, *f, *gp;
    cudaGetSymbolAddress((void**)&h,   g_h);
    cudaGetSymbolAddress((void**)&q,   g_q);
    cudaGetSymbolAddress((void**)&k,   g_k);
    cudaGetSymbolAddress((void**)&v,   g_v);
    cudaGetSymbolAddress((void**)&ctx, g_ctx);
    cudaGetSymbolAddress((void**)&t,   g_t);
    cudaGetSymbolAddress((void**)&f,   g_f);
    cudaGetSymbolAddress((void**)&gp,  g_gp);

    static int attr_done = 0;
    if (!attr_done) {
        cudaFuncSetAttribute(sw_attn_kernel,
                             cudaFuncAttributeMaxDynamicSharedMemorySize, AT_SMEM);
        attr_done = 1;
    }

    embed_ln_kernel<<<M_, 256>>>(ids, emb_tok, emb_pos, emb_ln_g, emb_ln_b, h);

    for (int l = 0; l < L_; l++) {
        const float* Wql = Wq + (size_t)l * D_ * D_;
        const float* Wkl = Wk + (size_t)l * D_ * D_;
        const float* Wvl = Wv + (size_t)l * D_ * D_;
        const float* Wol = Wo + (size_t)l * D_ * D_;
        const float* W1l = W1 + (size_t)l * D_ * F_;
        const float* W2l = W2 + (size_t)l * F_ * D_;

        dim3 gQKV(D_ / TBN, M_ / TBM, 3);
        dim3 gD(D_ / TBN, M_ / TBM, 1);
        dim3 gF(F_ / TBN, M_ / TBM, 1);

        gemm_tf32_kernel<<<gQKV, 256>>>(h,
            Wql, Wkl, Wvl,
            bq + l * D_, bk + l * D_, bv + l * D_,
            q, k, v,
            M_, D_, D_, 0, 0.125f, 1.0f, 1.0f);

        gattn_part_kernel<<<dim3(H_, B_, GNS), 128>>>(q, k, v, mask, gp);
        sw_attn_kernel<<<dim3(S_ / 16, H_, B_), 256, AT_SMEM>>>(q, k, v, mask, ctx);
        gattn_comb_kernel<<<dim3(H_, B_), 64>>>(gp, ctx);

        gemm_tf32_kernel<<<gD, 256>>>(ctx,
            Wol, Wol, Wol, bo + l * D_, bo + l * D_, bo + l * D_,
            t, t, t, M_, D_, D_, 0, 1.0f, 1.0f, 1.0f);
        add_ln_kernel<<<M_, 256>>>(h, t, ln1_g + l * D_, ln1_b + l * D_, h);

        gemm_tf32_kernel<<<gF, 256>>>(h,
            W1l, W1l, W1l, b1 + l * F_, b1 + l * F_, b1 + l * F_,
            f, f, f, M_, F_, D_, 1, 1.0f, 1.0f, 1.0f);
        gemm_tf32_kernel<<<gD, 256>>>(f,
            W2l, W2l, W2l, b2 + l * D_, b2 + l * D_, b2 + l * D_,
            t, t, t, M_, D_, F_, 0, 1.0f, 1.0f, 1.0f);
        add_ln_kernel<<<M_, 256>>>(h, t, ln2_g + l * D_, ln2_b + l * D_, h);
    }

    cls_kernel<<<1, 256>>>(h, clsW, clsb, (float*)d_out);
}

// round 15
// speedup vs baseline: 1.8250x; 1.0745x over previous
#include <cuda_runtime.h>
#include <math.h>

// ---------------- problem constants ----------------
#define B_  2
#define S_  4096
#define D_  768
#define H_  12
#define DH_ 64
#define L_  2
#define F_  3072
#define C_  256
#define M_  (B_*S_)
#define NEGV (-1000000000.0f)
#define GNS 32            // global-attn split chunks
#define GCK 128           // keys per chunk

// ---------------- scratch ----------------
__device__ float g_h  [M_ * D_];
__device__ float g_q  [M_ * D_];
__device__ float g_k  [M_ * D_];
__device__ float g_v  [M_ * D_];
__device__ float g_ctx[M_ * D_];
__device__ float g_t  [M_ * D_];
__device__ float g_f  [M_ * F_];
__device__ float g_gp [B_ * H_ * GNS * 66];   // per-chunk partials: 64 o + m + s

// ---------------- helpers ----------------
__device__ __forceinline__ float warp_sum(float v) {
    #pragma unroll
    for (int o = 16; o; o >>= 1) v += __shfl_xor_sync(0xffffffffu, v, o);
    return v;
}
__device__ __forceinline__ float warp_max(float v) {
    #pragma unroll
    for (int o = 16; o; o >>= 1) v = fmaxf(v, __shfl_xor_sync(0xffffffffu, v, o));
    return v;
}
__device__ float block_sum(float v, float* red) {
    int lane = threadIdx.x & 31, w = threadIdx.x >> 5;
    v = warp_sum(v);
    __syncthreads();
    if (lane == 0) red[w] = v;
    __syncthreads();
    int nw = (blockDim.x + 31) >> 5;
    float r = (threadIdx.x < nw) ? red[threadIdx.x] : 0.0f;
    if (w == 0) { r = warp_sum(r); if (lane == 0) red[0] = r; }
    __syncthreads();
    return red[0];
}
__device__ float block_max(float v, float* red) {
    int lane = threadIdx.x & 31, w = threadIdx.x >> 5;
    v = warp_max(v);
    __syncthreads();
    if (lane == 0) red[w] = v;
    __syncthreads();
    int nw = (blockDim.x + 31) >> 5;
    float r = (threadIdx.x < nw) ? red[threadIdx.x] : -INFINITY;
    if (w == 0) { r = warp_max(r); if (lane == 0) red[0] = r; }
    __syncthreads();
    return red[0];
}

__device__ __forceinline__ unsigned f2tf(float v) {
    unsigned r; asm("cvt.rna.tf32.f32 %0, %1;" : "=r"(r) : "f"(v)); return r;
}
__device__ __forceinline__ void mma_tf32(float* c, const unsigned* a, const unsigned* b) {
    asm volatile(
        "mma.sync.aligned.m16n8k8.row.col.f32.tf32.tf32.f32 "
        "{%0,%1,%2,%3},{%4,%5,%6,%7},{%8,%9},{%0,%1,%2,%3};\n"
        : "+f"(c[0]), "+f"(c[1]), "+f"(c[2]), "+f"(c[3])
        : "r"(a[0]), "r"(a[1]), "r"(a[2]), "r"(a[3]), "r"(b[0]), "r"(b[1]));
}
// cp.async with zero-fill: src_bytes < 16 zero-fills the remainder
__device__ __forceinline__ void cp_async16z(unsigned smem, const void* g, int src_bytes) {
    asm volatile("cp.async.ca.shared.global [%0], [%1], 16, %2;\n"
                 :: "r"(smem), "l"(g), "r"(src_bytes));
}

// ---------------- embedding + layernorm ----------------
__global__ void embed_ln_kernel(const int* __restrict__ ids,
                                const float* __restrict__ tok,
                                const float* __restrict__ pos,
                                const float* __restrict__ g,
                                const float* __restrict__ be,
                                float* __restrict__ out) {
    __shared__ float red[32];
    int row = blockIdx.x;
    int s = row % S_;
    int id = ids[row];
    const float* tp = tok + (size_t)id * D_;
    const float* pp = pos + (size_t)s  * D_;
    float vals[3]; float lsum = 0.0f;
    #pragma unroll
    for (int i = 0; i < 3; i++) {
        int c = threadIdx.x + i * 256;
        vals[i] = tp[c] + pp[c];
        lsum += vals[i];
    }
    float mean = block_sum(lsum, red) * (1.0f / D_);
    float lv = 0.0f;
    #pragma unroll
    for (int i = 0; i < 3; i++) { float d = vals[i] - mean; lv += d * d; }
    float var = block_sum(lv, red) * (1.0f / D_);
    float inv = rsqrtf(var + 1e-5f);
    float* op = out + (size_t)row * D_;
    #pragma unroll
    for (int i = 0; i < 3; i++) {
        int c = threadIdx.x + i * 256;
        op[c] = (vals[i] - mean) * inv * g[c] + be[c];
    }
}

// ---------------- residual add + layernorm ----------------
__global__ void add_ln_kernel(const float* __restrict__ x,
                              const float* __restrict__ r,
                              const float* __restrict__ g,
                              const float* __restrict__ be,
                              float* __restrict__ out) {
    __shared__ float red[32];
    int row = blockIdx.x;
    const float* xp = x + (size_t)row * D_;
    const float* rp = r + (size_t)row * D_;
    float vals[3]; float lsum = 0.0f;
    #pragma unroll
    for (int i = 0; i < 3; i++) {
        int c = threadIdx.x + i * 256;
        vals[i] = xp[c] + rp[c];
        lsum += vals[i];
    }
    float mean = block_sum(lsum, red) * (1.0f / D_);
    float lv = 0.0f;
    #pragma unroll
    for (int i = 0; i < 3; i++) { float d = vals[i] - mean; lv += d * d; }
    float var = block_sum(lv, red) * (1.0f / D_);
    float inv = rsqrtf(var + 1e-5f);
    float* op = out + (size_t)row * D_;
    #pragma unroll
    for (int i = 0; i < 3; i++) {
        int c = threadIdx.x + i * 256;
        op[c] = (vals[i] - mean) * inv * g[c] + be[c];
    }
}

// ---------------- tf32 mma GEMM (R3 layout; cvt at smem store) — FROZEN ----------------
#define TBM 128
#define TBN 128
#define TBK 16
#define ASTR 20
#define BSTR 132

__global__ __launch_bounds__(256) void gemm_tf32_kernel(
        const float* __restrict__ A,
        const float* __restrict__ W0, const float* __restrict__ W1p,
        const float* __restrict__ W2p,
        const float* __restrict__ bi0, const float* __restrict__ bi1,
        const float* __restrict__ bi2,
        float* __restrict__ C0, float* __restrict__ C1, float* __restrict__ C2,
        int M, int N, int K, int act, float s0, float s1, float s2) {
    __shared__ unsigned As[2][TBM * ASTR];
    __shared__ unsigned Bs[2][TBK * BSTR];

    int z = blockIdx.z;
    const float* W    = (z == 0) ? W0  : (z == 1) ? W1p : W2p;
    const float* bias = (z == 0) ? bi0 : (z == 1) ? bi1 : bi2;
    float*       Co   = (z == 0) ? C0  : (z == 1) ? C1  : C2;
    float scale       = (z == 0) ? s0  : (z == 1) ? s1  : s2;

    int tid = threadIdx.x;
    int lane = tid & 31, wid = tid >> 5;
    int wm = (wid & 3) * 32;
    int wn = (wid >> 2) * 64;
    int gid = lane >> 2, tig = lane & 3;
    size_t rowBase = (size_t)blockIdx.y * TBM;
    size_t colBase = (size_t)blockIdx.x * TBN;

    int s0i = tid, s1i = tid + 256;
    int ar0 = s0i >> 2, ac0 = (s0i & 3) * 4;
    int ar1 = s1i >> 2, ac1 = (s1i & 3) * 4;
    int br0 = s0i >> 5, bc0 = (s0i & 31) * 4;
    int br1 = s1i >> 5, bc1 = (s1i & 31) * 4;

    float c[2][8][4];
    #pragma unroll
    for (int mi = 0; mi < 2; mi++)
        #pragma unroll
        for (int ni = 0; ni < 8; ni++)
            #pragma unroll
            for (int q = 0; q < 4; q++) c[mi][ni][q] = 0.0f;

    int ntiles = K / TBK;

    float4 aPre0, aPre1, bPre0, bPre1;
    aPre0 = *(const float4*)&A[(rowBase + ar0) * K + ac0];
    aPre1 = *(const float4*)&A[(rowBase + ar1) * K + ac1];
    bPre0 = *(const float4*)&W[(size_t)br0 * N + colBase + bc0];
    bPre1 = *(const float4*)&W[(size_t)br1 * N + colBase + bc1];
    {
        unsigned* p;
        p = &As[0][ar0 * ASTR + ac0];
        p[0]=f2tf(aPre0.x); p[1]=f2tf(aPre0.y); p[2]=f2tf(aPre0.z); p[3]=f2tf(aPre0.w);
        p = &As[0][ar1 * ASTR + ac1];
        p[0]=f2tf(aPre1.x); p[1]=f2tf(aPre1.y); p[2]=f2tf(aPre1.z); p[3]=f2tf(aPre1.w);
        p = &Bs[0][br0 * BSTR + bc0];
        p[0]=f2tf(bPre0.x); p[1]=f2tf(bPre0.y); p[2]=f2tf(bPre0.z); p[3]=f2tf(bPre0.w);
        p = &Bs[0][br1 * BSTR + bc1];
        p[0]=f2tf(bPre1.x); p[1]=f2tf(bPre1.y); p[2]=f2tf(bPre1.z); p[3]=f2tf(bPre1.w);
    }
    __syncthreads();

    for (int kt = 0; kt < ntiles; kt++) {
        int cur = kt & 1;
        bool hasNext = (kt + 1) < ntiles;
        if (hasNext) {
            int k0 = (kt + 1) * TBK;
            aPre0 = *(const float4*)&A[(rowBase + ar0) * K + k0 + ac0];
            aPre1 = *(const float4*)&A[(rowBase + ar1) * K + k0 + ac1];
            bPre0 = *(const float4*)&W[(size_t)(k0 + br0) * N + colBase + bc0];
            bPre1 = *(const float4*)&W[(size_t)(k0 + br1) * N + colBase + bc1];
        }

        #pragma unroll
        for (int ks = 0; ks < 2; ks++) {
            int kb = ks * 8;
            unsigned af[2][4];
            #pragma unroll
            for (int mi = 0; mi < 2; mi++) {
                const unsigned* ap = &As[cur][(wm + mi * 16 + gid) * ASTR + kb + tig];
                af[mi][0] = ap[0];
                af[mi][1] = ap[8 * ASTR];
                af[mi][2] = ap[4];
                af[mi][3] = ap[8 * ASTR + 4];
            }
            unsigned bf[8][2];
            #pragma unroll
            for (int ni = 0; ni < 8; ni++) {
                const unsigned* bp = &Bs[cur][(kb + tig) * BSTR + wn + ni * 8 + gid];
                bf[ni][0] = bp[0];
                bf[ni][1] = bp[4 * BSTR];
            }
            #pragma unroll
            for (int mi = 0; mi < 2; mi++)
                #pragma unroll
                for (int ni = 0; ni < 8; ni++)
                    mma_tf32(c[mi][ni], af[mi], bf[ni]);
        }

        if (hasNext) {
            int nb = cur ^ 1;
            unsigned* p;
            p = &As[nb][ar0 * ASTR + ac0];
            p[0]=f2tf(aPre0.x); p[1]=f2tf(aPre0.y); p[2]=f2tf(aPre0.z); p[3]=f2tf(aPre0.w);
            p = &As[nb][ar1 * ASTR + ac1];
            p[0]=f2tf(aPre1.x); p[1]=f2tf(aPre1.y); p[2]=f2tf(aPre1.z); p[3]=f2tf(aPre1.w);
            p = &Bs[nb][br0 * BSTR + bc0];
            p[0]=f2tf(bPre0.x); p[1]=f2tf(bPre0.y); p[2]=f2tf(bPre0.z); p[3]=f2tf(bPre0.w);
            p = &Bs[nb][br1 * BSTR + bc1];
            p[0]=f2tf(bPre1.x); p[1]=f2tf(bPre1.y); p[2]=f2tf(bPre1.z); p[3]=f2tf(bPre1.w);
            __syncthreads();
        }
    }

    #pragma unroll
    for (int mi = 0; mi < 2; mi++) {
        size_t r0 = rowBase + wm + mi * 16 + gid;
        size_t r1 = r0 + 8;
        #pragma unroll
        for (int ni = 0; ni < 8; ni++) {
            size_t col = colBase + wn + ni * 8 + tig * 2;
            float b0 = bias[col], b1 = bias[col + 1];
            float v0 = (c[mi][ni][0] + b0) * scale;
            float v1 = (c[mi][ni][1] + b1) * scale;
            float v2 = (c[mi][ni][2] + b0) * scale;
            float v3 = (c[mi][ni][3] + b1) * scale;
            if (act == 1) {
                v0 = 0.5f * v0 * (1.0f + erff(v0 * 0.70710678f));
                v1 = 0.5f * v1 * (1.0f + erff(v1 * 0.70710678f));
                v2 = 0.5f * v2 * (1.0f + erff(v2 * 0.70710678f));
                v3 = 0.5f * v3 * (1.0f + erff(v3 * 0.70710678f));
            }
            *(float2*)&Co[r0 * N + col] = make_float2(v0, v1);
            *(float2*)&Co[r1 * N + col] = make_float2(v2, v3);
        }
    }
}

// ---------------- sliding-window attention, 16-query tiles, cp.async raw staging ----------------
// K tile natural [key][d] stride 68; V tile natural [key][d] stride 72 (PV B-frag conflict-free).
// No tf32 cvt anywhere: mma truncates fp32 -> tf32 in HW.
#define SCW2 772
#define AT_Q   0
#define AT_KV  1088
#define AT_SC  5696
#define AT_INV 18048
#define AT_MV  18064
#define AT_SMEM (18132 * 4)

__global__ __launch_bounds__(256, 3) void sw_attn_kernel(
        const float* __restrict__ q,
        const float* __restrict__ k,
        const float* __restrict__ v,
        const int* __restrict__ mask,
        float* __restrict__ ctx) {
    extern __shared__ float sm[];
    float* qS  = sm + AT_Q;
    float* kvS = sm + AT_KV;
    float* sc  = sm + AT_SC;
    float* inv = sm + AT_INV;
    float* mv  = sm + AT_MV;
    unsigned* scU = (unsigned*)sc;

    int tid = threadIdx.x;
    int lane = tid & 31, w = tid >> 5;
    int gid = lane >> 2, ti = lane & 3;
    int h = blockIdx.y, b = blockIdx.z;
    int qbase = blockIdx.x * 16;
    int n = qbase / C_;
    int cbase = qbase % C_;
    int j0 = (n - 1) * C_;
    int n0 = w * 8;

    int ktlo = cbase >> 6;
    int kthi = (cbase + 2 * C_ + 15) >> 6;
    int klo = ktlo * 64, khi = kthi * 64 + 63;

    // stage q raw [q][d], stride 68
    {
        int r = tid >> 4, c4 = (tid & 15) * 4;
        *(float4*)&qS[r * 68 + c4] =
            *(const float4*)&q[((size_t)(b * S_ + qbase + r)) * D_ + h * DH_ + c4];
    }
    __syncthreads();

    // hoist Q fragments (raw fp32 bits; mma truncates)
    unsigned aF[8][4];
    #pragma unroll
    for (int ks = 0; ks < 8; ks++) {
        const float* ap = &qS[gid * 68 + ks * 8 + ti];
        aF[ks][0] = __float_as_uint(ap[0]);
        aF[ks][1] = __float_as_uint(ap[8 * 68]);
        aF[ks][2] = __float_as_uint(ap[4]);
        aF[ks][3] = __float_as_uint(ap[8 * 68 + 4]);
    }

    // ---- score phase ----
    for (int kt = ktlo; kt <= kthi; kt++) {
        __syncthreads();
        #pragma unroll
        for (int p = 0; p < 4; p++) {
            int s = tid + p * 256;
            int r = s >> 4, c4 = (s & 15) * 4;
            int j = j0 + kt * 64 + r;
            bool inr = (j >= 0) && (j < S_);
            const float* src = &k[((size_t)(b * S_ + (inr ? j : 0))) * D_ + h * DH_ + c4];
            unsigned sa = (unsigned)__cvta_generic_to_shared(&kvS[r * 68 + c4]);
            cp_async16z(sa, src, inr ? 16 : 0);
        }
        if (tid < 64) {
            int j = j0 + kt * 64 + tid;
            mv[tid] = (j > 0 && j < S_ && mask[b * S_ + j] > 0) ? 1.0f : 0.0f;
        }
        asm volatile("cp.async.commit_group;\n");
        asm volatile("cp.async.wait_group 0;\n");
        __syncthreads();

        float cS[4] = {0.f, 0.f, 0.f, 0.f};
        #pragma unroll
        for (int ks = 0; ks < 8; ks++) {
            unsigned bb[2];
            bb[0] = __float_as_uint(kvS[(n0 + gid) * 68 + ks * 8 + ti]);
            bb[1] = __float_as_uint(kvS[(n0 + gid) * 68 + ks * 8 + ti + 4]);
            mma_tf32(cS, aF[ks], bb);
        }

        int kk0 = kt * 64 + n0 + 2 * ti;
        float valid0 = mv[n0 + 2 * ti], valid1 = mv[n0 + 2 * ti + 1];
        int r0 = gid, r1 = gid + 8;
        int cq0 = cbase + r0, cq1 = cbase + r1;
        bool ok00 = (valid0 > 0.5f) && (kk0 >= cq0) && (kk0 <= cq0 + 2 * C_);
        bool ok01 = (valid1 > 0.5f) && (kk0 + 1 >= cq0) && (kk0 + 1 <= cq0 + 2 * C_);
        bool ok10 = (valid0 > 0.5f) && (kk0 >= cq1) && (kk0 <= cq1 + 2 * C_);
        bool ok11 = (valid1 > 0.5f) && (kk0 + 1 >= cq1) && (kk0 + 1 <= cq1 + 2 * C_);
        sc[r0 * SCW2 + kk0]     = ok00 ? cS[0] : NEGV;
        sc[r0 * SCW2 + kk0 + 1] = ok01 ? cS[1] : NEGV;
        sc[r1 * SCW2 + kk0]     = ok10 ? cS[2] : NEGV;
        sc[r1 * SCW2 + kk0 + 1] = ok11 ? cS[3] : NEGV;
    }

    // global-token score (16 rows)
    if (tid < 16) {
        float acc = 0.0f;
        const float* k0p = k + ((size_t)(b * S_)) * D_ + h * DH_;
        #pragma unroll 8
        for (int d = 0; d < 64; d++)
            acc = fmaf(qS[tid * 68 + d], k0p[d], acc);
        sc[tid * SCW2 + 3 * C_] = (mask[b * S_] > 0) ? acc : NEGV;
    }
    __syncthreads();

    // ---- softmax, clipped range; probs stay raw fp32 ----
    for (int rr = 0; rr < 2; rr++) {
        int qi = w + rr * 8;
        float* row = sc + qi * SCW2;
        float m = -INFINITY;
        for (int j = klo + lane; j <= khi; j += 32) m = fmaxf(m, row[j]);
        if (lane == 0) m = fmaxf(m, row[3 * C_]);
        m = warp_max(m);
        float ssum = 0.0f;
        for (int j = klo + lane; j <= khi; j += 32) {
            float e = __expf(row[j] - m);
            ssum += e;
            row[j] = e;
        }
        if (lane == 0) {
            float e = __expf(row[3 * C_] - m);
            ssum += e;
            row[3 * C_] = e;
        }
        ssum = warp_sum(ssum);
        if (lane == 0) inv[qi] = 1.0f / ssum;
    }

    // ---- PV phase (V natural layout, stride 72) ----
    float cO[4] = {0.f, 0.f, 0.f, 0.f};
    for (int kt = ktlo; kt <= kthi; kt++) {
        __syncthreads();
        #pragma unroll
        for (int p = 0; p < 4; p++) {
            int s = tid + p * 256;
            int r = s >> 4, c4 = (s & 15) * 4;
            int j = j0 + kt * 64 + r;
            bool inr = (j >= 0) && (j < S_);
            const float* src = &v[((size_t)(b * S_ + (inr ? j : 0))) * D_ + h * DH_ + c4];
            unsigned sa = (unsigned)__cvta_generic_to_shared(&kvS[r * 72 + c4]);
            cp_async16z(sa, src, inr ? 16 : 0);
        }
        asm volatile("cp.async.commit_group;\n");
        asm volatile("cp.async.wait_group 0;\n");
        __syncthreads();

        #pragma unroll
        for (int ks = 0; ks < 8; ks++) {
            unsigned bb[2];
            bb[0] = __float_as_uint(kvS[(ks * 8 + ti) * 72 + n0 + gid]);
            bb[1] = __float_as_uint(kvS[(ks * 8 + ti + 4) * 72 + n0 + gid]);
            unsigned aa[4];
            const unsigned* pp = &scU[gid * SCW2 + kt * 64 + ks * 8 + ti];
            aa[0] = pp[0];
            aa[1] = pp[8 * SCW2];
            aa[2] = pp[4];
            aa[3] = pp[8 * SCW2 + 4];
            mma_tf32(cO, aa, bb);
        }
    }

    // add global-token contribution and write
    {
        const float* v0p = v + ((size_t)(b * S_)) * D_ + h * DH_;
        int d0 = n0 + 2 * ti;
        float gv0 = v0p[d0], gv1 = v0p[d0 + 1];
        int r0 = gid, r1 = gid + 8;
        float g0 = sc[r0 * SCW2 + 3 * C_], g1 = sc[r1 * SCW2 + 3 * C_];
        float i0 = inv[r0], i1 = inv[r1];
        float2 o0 = make_float2((cO[0] + g0 * gv0) * i0,
                                (cO[1] + g0 * gv1) * i0);
        float2 o1 = make_float2((cO[2] + g1 * gv0) * i1,
                                (cO[3] + g1 * gv1) * i1);
        *(float2*)&ctx[((size_t)(b * S_ + qbase + r0)) * D_ + h * DH_ + d0] = o0;
        *(float2*)&ctx[((size_t)(b * S_ + qbase + r1)) * D_ + h * DH_ + d0] = o1;
    }
}

// ---------------- global-row attention, split-KV ----------------
__global__ __launch_bounds__(128) void gattn_part_kernel(
        const float* __restrict__ q,
        const float* __restrict__ k,
        const float* __restrict__ v,
        const int* __restrict__ mask,
        float* __restrict__ part) {
    __shared__ float qs[64];
    __shared__ float red[32];
    __shared__ float ps[GCK];
    int h = blockIdx.x, b = blockIdx.y, ch = blockIdx.z;
    int tid = threadIdx.x;
    const float* qp = q + ((size_t)(b * S_)) * D_ + h * DH_;
    if (tid < 16) ((float4*)qs)[tid] = ((const float4*)qp)[tid];
    __syncthreads();

    int j = ch * GCK + tid;
    float s = NEGV;
    if (mask[b * S_ + j] > 0) {
        const float4* kp = (const float4*)(k + ((size_t)(b * S_ + j)) * D_ + h * DH_);
        float acc = 0.0f;
        #pragma unroll
        for (int d4 = 0; d4 < 16; d4++) {
            float4 kv = kp[d4];
            float4 qv = ((const float4*)qs)[d4];
            acc += kv.x * qv.x + kv.y * qv.y + kv.z * qv.z + kv.w * qv.w;
        }
        s = acc;
    }
    float m = block_max(s, red);
    float e = __expf(s - m);
    float ssum = block_sum(e, red);
    ps[tid] = e;
    __syncthreads();

    float* op = part + ((size_t)(b * H_ + h) * GNS + ch) * 66;
    if (tid < 64) {
        float acc = 0.0f;
        const float* vp = v + ((size_t)(b * S_ + ch * GCK)) * D_ + h * DH_ + tid;
        #pragma unroll 4
        for (int kk = 0; kk < GCK; kk++)
            acc = fmaf(ps[kk], vp[(size_t)kk * D_], acc);
        op[tid] = acc;
    } else if (tid == 64) {
        op[64] = m;
        op[65] = ssum;
    }
}

__global__ __launch_bounds__(64) void gattn_comb_kernel(
        const float* __restrict__ part,
        float* __restrict__ ctx) {
    int h = blockIdx.x, b = blockIdx.y;
    int tid = threadIdx.x;
    const float* pp = part + ((size_t)(b * H_ + h) * GNS) * 66;
    float M = -INFINITY;
    #pragma unroll
    for (int i = 0; i < GNS; i++) M = fmaxf(M, pp[i * 66 + 64]);
    float S = 0.0f, acc = 0.0f;
    #pragma unroll
    for (int i = 0; i < GNS; i++) {
        float wgt = __expf(pp[i * 66 + 64] - M);
        S += pp[i * 66 + 65] * wgt;
        acc += pp[i * 66 + tid] * wgt;
    }
    ctx[((size_t)(b * S_)) * D_ + h * DH_ + tid] = acc / S;
}

// ---------------- classifier head ----------------
__global__ void cls_kernel(const float* __restrict__ h,
                           const float* __restrict__ W,
                           const float* __restrict__ bias,
                           float* __restrict__ out) {
    int w = threadIdx.x >> 5, lane = threadIdx.x & 31;
    if (w < B_ * 3) {
        int b = w / 3, c = w % 3;
        float acc = 0.0f;
        for (int kx = lane; kx < D_; kx += 32)
            acc += h[((size_t)(b * S_)) * D_ + kx] * W[kx * 3 + c];
        acc = warp_sum(acc);
        if (lane == 0) out[b * 3 + c] = acc + bias[c];
    }
}

// ---------------- launch ----------------
extern "C" void kernel_launch(void* const* d_in, const int* in_sizes, int n_in,
                              void* d_out, int out_size) {
    const int*   ids      = (const int*)d_in[0];
    const int*   mask     = (const int*)d_in[1];
    const float* emb_tok  = (const float*)d_in[2];
    const float* emb_pos  = (const float*)d_in[3];
    const float* emb_ln_g = (const float*)d_in[4];
    const float* emb_ln_b = (const float*)d_in[5];
    const float* Wq = (const float*)d_in[6];
    const float* bq = (const float*)d_in[7];
    const float* Wk = (const float*)d_in[8];
    const float* bk = (const float*)d_in[9];
    const float* Wv = (const float*)d_in[10];
    const float* bv = (const float*)d_in[11];
    const float* Wo = (const float*)d_in[12];
    const float* bo = (const float*)d_in[13];
    const float* ln1_g = (const float*)d_in[14];
    const float* ln1_b = (const float*)d_in[15];
    const float* W1 = (const float*)d_in[16];
    const float* b1 = (const float*)d_in[17];
    const float* W2 = (const float*)d_in[18];
    const float* b2 = (const float*)d_in[19];
    const float* ln2_g = (const float*)d_in[20];
    const float* ln2_b = (const float*)d_in[21];
    const float* clsW = (const float*)d_in[22];
    const float* clsb = (const float*)d_in[23];

    float *h, *q, *k, *v, *ctx, *t, *f, *gp;
    cudaGetSymbolAddress((void**)&h,   g_h);
    cudaGetSymbolAddress((void**)&q,   g_q);
    cudaGetSymbolAddress((void**)&k,   g_k);
    cudaGetSymbolAddress((void**)&v,   g_v);
    cudaGetSymbolAddress((void**)&ctx, g_ctx);
    cudaGetSymbolAddress((void**)&t,   g_t);
    cudaGetSymbolAddress((void**)&f,   g_f);
    cudaGetSymbolAddress((void**)&gp,  g_gp);

    static int attr_done = 0;
    if (!attr_done) {
        cudaFuncSetAttribute(sw_attn_kernel,
                             cudaFuncAttributeMaxDynamicSharedMemorySize, AT_SMEM);
        attr_done = 1;
    }

    embed_ln_kernel<<<M_, 256>>>(ids, emb_tok, emb_pos, emb_ln_g, emb_ln_b, h);

    for (int l = 0; l < L_; l++) {
        const float* Wql = Wq + (size_t)l * D_ * D_;
        const float* Wkl = Wk + (size_t)l * D_ * D_;
        const float* Wvl = Wv + (size_t)l * D_ * D_;
        const float* Wol = Wo + (size_t)l * D_ * D_;
        const float* W1l = W1 + (size_t)l * D_ * F_;
        const float* W2l = W2 + (size_t)l * F_ * D_;

        dim3 gQKV(D_ / TBN, M_ / TBM, 3);
        dim3 gD(D_ / TBN, M_ / TBM, 1);
        dim3 gF(F_ / TBN, M_ / TBM, 1);

        gemm_tf32_kernel<<<gQKV, 256>>>(h,
            Wql, Wkl, Wvl,
            bq + l * D_, bk + l * D_, bv + l * D_,
            q, k, v,
            M_, D_, D_, 0, 0.125f, 1.0f, 1.0f);

        gattn_part_kernel<<<dim3(H_, B_, GNS), 128>>>(q, k, v, mask, gp);
        sw_attn_kernel<<<dim3(S_ / 16, H_, B_), 256, AT_SMEM>>>(q, k, v, mask, ctx);
        gattn_comb_kernel<<<dim3(H_, B_), 64>>>(gp, ctx);

        gemm_tf32_kernel<<<gD, 256>>>(ctx,
            Wol, Wol, Wol, bo + l * D_, bo + l * D_, bo + l * D_,
            t, t, t, M_, D_, D_, 0, 1.0f, 1.0f, 1.0f);
        add_ln_kernel<<<M_, 256>>>(h, t, ln1_g + l * D_, ln1_b + l * D_, h);

        gemm_tf32_kernel<<<gF, 256>>>(h,
            W1l, W1l, W1l, b1 + l * F_, b1 + l * F_, b1 + l * F_,
            f, f, f, M_, F_, D_, 1, 1.0f, 1.0f, 1.0f);
        gemm_tf32_kernel<<<gD, 256>>>(f,
            W2l, W2l, W2l, b2 + l * D_, b2 + l * D_, b2 + l * D_,
            t, t, t, M_, D_, F_, 0, 1.0f, 1.0f, 1.0f);
        add_ln_kernel<<<M_, 256>>>(h, t, ln2_g + l * D_, ln2_b + l * D_, h);
    }

    cls_kernel<<<1, 256>>>(h, clsW, clsb, (float*)d_out);
}